// round 12
// baseline (speedup 1.0000x reference)
#include <cuda_runtime.h>
#include <cuda_fp16.h>
#include <math.h>
#include <stdint.h>

#define D_MODEL 1024
#define HEADS   16
#define DH      64
#define BATCH   4
#define SEQ     2048
#define M_TOTAL (BATCH * SEQ)   // 8192

// ---------------- scratch (device globals: allocation-guard safe) ----------------
__device__ __half g_qh[(size_t)BATCH * HEADS * SEQ * DH];   // [B,H,L,Dh] fp16 (q pre-scaled)
__device__ __half g_kh[(size_t)BATCH * HEADS * SEQ * DH];
__device__ __half g_vh[(size_t)BATCH * HEADS * SEQ * DH];
__device__ __half g_att[(size_t)M_TOTAL * D_MODEL];         // [B*L, D_MODEL] fp16
__device__ __half g_qc[(size_t)M_TOTAL * D_MODEL];          // fp16 inputs
__device__ __half g_kc[(size_t)M_TOTAL * D_MODEL];
__device__ __half g_vc[(size_t)M_TOTAL * D_MODEL];
__device__ __half g_Wt[(size_t)4 * D_MODEL * D_MODEL];      // fp16, transposed [n][k]

// ---------------- helpers ----------------
__device__ __forceinline__ uint32_t smem_u32(const void* p) {
    uint32_t a;
    asm("{ .reg .u64 t; cvta.to.shared.u64 t, %1; cvt.u32.u64 %0, t; }" : "=r"(a) : "l"(p));
    return a;
}

__device__ __forceinline__ uint32_t pack_h2(float lo, float hi) {
    uint32_t r;
    asm("cvt.rn.f16x2.f32 %0, %1, %2;" : "=r"(r) : "f"(hi), "f"(lo));
    return r;
}

__device__ __forceinline__ void mma_f16(float c[4], const uint32_t a[4], const uint32_t b[2]) {
    asm("mma.sync.aligned.m16n8k16.row.col.f32.f16.f16.f32 "
        "{%0,%1,%2,%3}, {%4,%5,%6,%7}, {%8,%9}, {%0,%1,%2,%3};"
        : "+f"(c[0]), "+f"(c[1]), "+f"(c[2]), "+f"(c[3])
        : "r"(a[0]), "r"(a[1]), "r"(a[2]), "r"(a[3]), "r"(b[0]), "r"(b[1]));
}

__device__ __forceinline__ void ldsm4(uint32_t r[4], uint32_t saddr) {
    asm volatile("ldmatrix.sync.aligned.m8n8.x4.shared.b16 {%0,%1,%2,%3}, [%4];"
        : "=r"(r[0]), "=r"(r[1]), "=r"(r[2]), "=r"(r[3]) : "r"(saddr));
}

__device__ __forceinline__ void ldsm4t(uint32_t r[4], uint32_t saddr) {
    asm volatile("ldmatrix.sync.aligned.m8n8.x4.trans.shared.b16 {%0,%1,%2,%3}, [%4];"
        : "=r"(r[0]), "=r"(r[1]), "=r"(r[2]), "=r"(r[3]) : "r"(saddr));
}

#define CPA16(dst, src) asm volatile("cp.async.cg.shared.global [%0], [%1], 16;" :: "r"(dst), "l"(src))
#define CPA_COMMIT()    asm volatile("cp.async.commit_group;")
#define CPA_WAIT1()     asm volatile("cp.async.wait_group 1;")
#define CPA_WAIT0()     asm volatile("cp.async.wait_group 0;")

// ---------------- prologue converts ----------------
__global__ __launch_bounds__(256) void tohalf3(
    const float* __restrict__ a, const float* __restrict__ b, const float* __restrict__ c,
    __half* __restrict__ oa, __half* __restrict__ ob, __half* __restrict__ oc)
{
    const int z = blockIdx.z;
    const float* in = (z == 0) ? a : (z == 1) ? b : c;
    __half* out     = (z == 0) ? oa : (z == 1) ? ob : oc;
    const size_t i = ((size_t)blockIdx.x * 256 + threadIdx.x) * 4;
    float4 v = *(const float4*)(in + i);
    uint2 u = { pack_h2(v.x, v.y), pack_h2(v.z, v.w) };
    *(uint2*)(out + i) = u;
}

__global__ __launch_bounds__(256) void transpose_half4(
    const float* __restrict__ w0, const float* __restrict__ w1,
    const float* __restrict__ w2, const float* __restrict__ w3,
    __half* __restrict__ outbase)
{
    const int z = blockIdx.z;
    const float* in = (z == 0) ? w0 : (z == 1) ? w1 : (z == 2) ? w2 : w3;
    __half* out = outbase + (size_t)z * D_MODEL * D_MODEL;

    __shared__ float tile[32][33];
    const int tx = threadIdx.x & 31, ty = threadIdx.x >> 5;   // 32x8
    const int x = blockIdx.x * 32 + tx;
    const int y = blockIdx.y * 32 + ty;
#pragma unroll
    for (int j = 0; j < 32; j += 8)
        tile[ty + j][tx] = in[(size_t)(y + j) * D_MODEL + x];   // in[k][n]
    __syncthreads();
    const int x2 = blockIdx.y * 32 + tx;
    const int y2 = blockIdx.x * 32 + ty;
#pragma unroll
    for (int j = 0; j < 32; j += 8)
        out[(size_t)(y2 + j) * D_MODEL + x2] = __float2half_rn(tile[tx][ty + j]);  // out[n][k]
}

// ---------------- FP16 GEMM: CTA 128x256, warp 64x64, 3-stage cp.async ----------------
#define SSTR 72                         // fp16 per row (64 data + 8 pad) = 144B
#define A_ROWS 128
#define B_ROWS 256
#define ST_A_HALF (A_ROWS * SSTR)
#define STAGE_B ((A_ROWS + B_ROWS) * SSTR * 2)   // 55296
#define GEMM_SMEM_B (3 * STAGE_B)                // 165888

template <int HEADSPLIT>
__global__ __launch_bounds__(256) void gemm_fp16(
    const __half* __restrict__ A0, const __half* __restrict__ A1, const __half* __restrict__ A2,
    const __half* __restrict__ T0, const __half* __restrict__ T1, const __half* __restrict__ T2,
    const float* __restrict__ b0, const float* __restrict__ b1, const float* __restrict__ b2,
    void* __restrict__ C0, void* __restrict__ C1, void* __restrict__ C2)
{
    const int z = blockIdx.z;
    const __half* A   = (z == 0) ? A0 : (z == 1) ? A1 : A2;
    const __half* Wt  = (z == 0) ? T0 : (z == 1) ? T1 : T2;
    const float* bias = (z == 0) ? b0 : (z == 1) ? b1 : b2;
    void* C           = (z == 0) ? C0 : (z == 1) ? C1 : C2;
    const float oscale = (HEADSPLIT && z == 0) ? 0.125f : 1.0f;   // fold 1/sqrt(Dh) into q

    extern __shared__ __half sh[];
    const uint32_t sbase = smem_u32(sh);
    const int tid = threadIdx.x;
    const int lane = tid & 31;
    const int w = tid >> 5;
    const int g = lane >> 2, t = lane & 3;
    const int wm = w >> 2, wn = w & 3;           // 2 x 4 warps -> 64x64 tiles
    const int bm = blockIdx.y * 128, bn = blockIdx.x * 256;

    float acc[4][8][4];
#pragma unroll
    for (int mt = 0; mt < 4; mt++)
#pragma unroll
        for (int nt = 0; nt < 8; nt++)
#pragma unroll
            for (int i = 0; i < 4; i++) acc[mt][nt][i] = 0.f;

    // cp.async: A row tid>>1 (half tid&1); B rows tid>>1 and +128 (half tid&1)
    const int srow = tid >> 1;
    const int soff = (tid & 1) << 5;
    const __half* Ag  = A  + (size_t)(bm + srow) * D_MODEL + soff;
    const __half* Bg0 = Wt + (size_t)(bn + srow) * D_MODEL + soff;
    const __half* Bg1 = Bg0 + (size_t)128 * D_MODEL;
    const uint32_t ad0  = sbase + (uint32_t)(srow * SSTR + soff) * 2u;
    const uint32_t bd0  = ad0 + (uint32_t)ST_A_HALF * 2u;
    const uint32_t bd1  = bd0 + (uint32_t)(128 * SSTR) * 2u;

    // prologue: tiles 0,1 -> stages 0,1 (two commit groups)
#pragma unroll
    for (int p = 0; p < 2; p++) {
        const int k0 = p * 64;
        const uint32_t so = (uint32_t)(p * STAGE_B);
#pragma unroll
        for (int j = 0; j < 4; j++) CPA16(ad0 + so + j * 16, Ag + k0 + j * 8);
#pragma unroll
        for (int j = 0; j < 4; j++) CPA16(bd0 + so + j * 16, Bg0 + k0 + j * 8);
#pragma unroll
        for (int j = 0; j < 4; j++) CPA16(bd1 + so + j * 16, Bg1 + k0 + j * 8);
        CPA_COMMIT();
    }

    // fragment bases
    const int lrow = (lane & 7) + ((lane >> 3) & 1) * 8;
    const uint32_t a_frag0 = sbase + (uint32_t)(((wm * 64) + lrow) * SSTR + (lane >> 4) * 8) * 2u;
    const int bn_lane = (lane & 7) + (lane >> 4) * 8;
    const int k_lane = ((lane >> 3) & 1) * 8;
    const uint32_t b_frag0 = sbase + (uint32_t)ST_A_HALF * 2u
                           + (uint32_t)((wn * 64 + bn_lane) * SSTR + k_lane) * 2u;

    int s = 0;                       // compute stage
    int s2 = 2;                      // prefetch stage = (s+2)%3
    for (int i = 0; i < 16; i++) {
        if (i + 1 < 16) { CPA_WAIT1(); } else { CPA_WAIT0(); }
        __syncthreads();
        if (i + 2 < 16) {
            const int k0 = (i + 2) * 64;
            const uint32_t so = (uint32_t)(s2 * STAGE_B);
#pragma unroll
            for (int j = 0; j < 4; j++) CPA16(ad0 + so + j * 16, Ag + k0 + j * 8);
#pragma unroll
            for (int j = 0; j < 4; j++) CPA16(bd0 + so + j * 16, Bg0 + k0 + j * 8);
#pragma unroll
            for (int j = 0; j < 4; j++) CPA16(bd1 + so + j * 16, Bg1 + k0 + j * 8);
            CPA_COMMIT();
        }
        const uint32_t so = (uint32_t)(s * STAGE_B);
        const uint32_t ab = a_frag0 + so;
        const uint32_t bb = b_frag0 + so;
#pragma unroll
        for (int ks = 0; ks < 4; ks++) {
            uint32_t a[4][4], b[8][2];
#pragma unroll
            for (int mt = 0; mt < 4; mt++)
                ldsm4(a[mt], ab + (uint32_t)(mt * 16 * SSTR) * 2u + ks * 32);
#pragma unroll
            for (int p = 0; p < 4; p++) {
                uint32_t r4[4];
                ldsm4(r4, bb + (uint32_t)(p * 16 * SSTR) * 2u + ks * 32);
                b[2 * p][0] = r4[0];     b[2 * p][1] = r4[1];
                b[2 * p + 1][0] = r4[2]; b[2 * p + 1][1] = r4[3];
            }
#pragma unroll
            for (int mt = 0; mt < 4; mt++)
#pragma unroll
                for (int nt = 0; nt < 8; nt++)
                    mma_f16(acc[mt][nt], a[mt], b[nt]);
        }
        if (++s == 3) s = 0;
        if (++s2 == 3) s2 = 0;
    }

    // epilogue
#pragma unroll
    for (int mt = 0; mt < 4; mt++) {
#pragma unroll
        for (int nt = 0; nt < 8; nt++) {
            const int r0 = bm + wm * 64 + mt * 16 + g;
            const int c0 = bn + wn * 64 + nt * 8 + 2 * t;
#pragma unroll
            for (int i = 0; i < 4; i++) {
                const int row = r0 + (i >> 1) * 8;
                const int col = c0 + (i & 1);
                const float v = (acc[mt][nt][i] + bias[col]) * oscale;
                if (HEADSPLIT) {
                    const int b = row >> 11, l = row & (SEQ - 1);
                    const int h = col >> 6,  d = col & 63;
                    ((__half*)C)[(((size_t)(b * HEADS + h) * SEQ + l) << 6) + d] =
                        __float2half_rn(v);
                } else {
                    ((float*)C)[(size_t)row * D_MODEL + col] = v;
                }
            }
        }
    }
}

// ---------------- FP16 flash attention: 3-buffer cp.async, ldsm Q/K, ldsm.trans V ----------------
// BQ=128, BK=64, 256 threads, warp = 16 q-rows. Q arrives pre-scaled by 0.125.
#define FSTR 72
#define QB_BYTES (128 * FSTR * 2)        // 18432
#define KB_BYTES (64 * FSTR * 2)         // 9216
#define KVBUF_B (2 * KB_BYTES)           // K then V per buffer
#define FLASH_SMEM_B (QB_BYTES + 3 * KVBUF_B)  // 73728

__global__ __launch_bounds__(256) void flash_fp16(
    const __half* __restrict__ Q, const __half* __restrict__ K,
    const __half* __restrict__ V, __half* __restrict__ O)
{
    extern __shared__ __half sm[];
    const uint32_t sbase = smem_u32(sm);
    const uint32_t kvbase = sbase + QB_BYTES;

    const int tid = threadIdx.x;
    const int lane = tid & 31;
    const int w = tid >> 5;
    const int g = lane >> 2, t = lane & 3;
    const int bh = blockIdx.y;
    const int bx = blockIdx.x;
    const int q0 = bx * 128;

    const __half* Qb = Q + (size_t)bh * SEQ * DH;
    const __half* Kb = K + (size_t)bh * SEQ * DH;
    const __half* Vb = V + (size_t)bh * SEQ * DH;

    const int qrow = tid >> 1, qoff = (tid & 1) * 32;
    const int krow = tid >> 2, koff = (tid & 3) * 16;
    const uint32_t qdst0 = sbase  + (uint32_t)(qrow * FSTR + qoff) * 2u;
    const uint32_t kdst0 = kvbase + (uint32_t)(krow * FSTR + koff) * 2u;
    const uint32_t vdst0 = kdst0 + (uint32_t)KB_BYTES;
    const __half* Qg = Qb + (size_t)(q0 + qrow) * DH + qoff;
    const __half* Kg = Kb + (size_t)krow * DH + koff;
    const __half* Vg = Vb + (size_t)krow * DH + koff;

    const int jmax = 2 * bx + 1;

    // prologue: group0 = Q + KV tile0, group1 = KV tile1
#pragma unroll
    for (int j = 0; j < 4; j++) CPA16(qdst0 + j * 16, Qg + j * 8);
#pragma unroll
    for (int j = 0; j < 2; j++) CPA16(kdst0 + j * 16, Kg + j * 8);
#pragma unroll
    for (int j = 0; j < 2; j++) CPA16(vdst0 + j * 16, Vg + j * 8);
    CPA_COMMIT();
    {
        const size_t koffg = (size_t)64 * DH;
#pragma unroll
        for (int j = 0; j < 2; j++) CPA16(kdst0 + KVBUF_B + j * 16, Kg + koffg + j * 8);
#pragma unroll
        for (int j = 0; j < 2; j++) CPA16(vdst0 + KVBUF_B + j * 16, Vg + koffg + j * 8);
        CPA_COMMIT();
    }

    const int lrow = (lane & 7) + ((lane >> 3) & 1) * 8;
    const uint32_t q_frag0 = sbase + (uint32_t)((w * 16 + lrow) * FSTR + (lane >> 4) * 8) * 2u;
    const int bn_lane = (lane & 7) + (lane >> 4) * 8;
    const int k_lane = ((lane >> 3) & 1) * 8;
    const uint32_t k_frag0 = kvbase + (uint32_t)(bn_lane * FSTR + k_lane) * 2u;
    const uint32_t v_frag0 = kvbase + (uint32_t)KB_BYTES
                           + (uint32_t)(lrow * FSTR + (lane >> 4) * 8) * 2u;

    float oacc[8][4];
#pragma unroll
    for (int dt = 0; dt < 8; dt++)
#pragma unroll
        for (int i = 0; i < 4; i++) oacc[dt][i] = 0.f;
    float m0 = -INFINITY, m1 = -INFINITY, l0 = 0.f, l1 = 0.f;

    const int qr = q0 + w * 16 + g;

    int buf = 0, pbuf = 2;   // compute buffer, prefetch buffer = (buf+2)%3
    for (int j = 0; j <= jmax; j++) {
        if (j + 1 <= jmax) { CPA_WAIT1(); } else { CPA_WAIT0(); }
        __syncthreads();
        if (j + 2 <= jmax) {
            const size_t koffg = (size_t)(j + 2) * 64 * DH;
            const uint32_t bo = (uint32_t)(pbuf * KVBUF_B);
#pragma unroll
            for (int jj = 0; jj < 2; jj++)
                CPA16(kdst0 + bo + jj * 16, Kg + koffg + jj * 8);
#pragma unroll
            for (int jj = 0; jj < 2; jj++)
                CPA16(vdst0 + bo + jj * 16, Vg + koffg + jj * 8);
            CPA_COMMIT();
        }
        const uint32_t kf = k_frag0 + (uint32_t)(buf * KVBUF_B);
        const uint32_t vf = v_frag0 + (uint32_t)(buf * KVBUF_B);
        const int k0 = j * 64;

        // S = Q K^T (Q pre-scaled)
        float sacc[8][4];
#pragma unroll
        for (int nt = 0; nt < 8; nt++)
#pragma unroll
            for (int i = 0; i < 4; i++) sacc[nt][i] = 0.f;
#pragma unroll
        for (int kt = 0; kt < 4; kt++) {
            uint32_t qf[4];
            ldsm4(qf, q_frag0 + kt * 32);
            uint32_t kb[8][2];
#pragma unroll
            for (int p = 0; p < 4; p++) {
                uint32_t r4[4];
                ldsm4(r4, kf + (uint32_t)(p * 16 * FSTR) * 2u + kt * 32);
                kb[2 * p][0] = r4[0];     kb[2 * p][1] = r4[1];
                kb[2 * p + 1][0] = r4[2]; kb[2 * p + 1][1] = r4[3];
            }
#pragma unroll
            for (int nt = 0; nt < 8; nt++)
                mma_f16(sacc[nt], qf, kb[nt]);
        }

        // causal mask: only on the two diagonal-adjacent tiles
        if (j >= 2 * bx) {
#pragma unroll
            for (int nt = 0; nt < 8; nt++) {
                const int c0 = k0 + nt * 8 + 2 * t;
#pragma unroll
                for (int i = 0; i < 4; i++) {
                    const int row = (i >> 1) ? qr + 8 : qr;
                    const int col = c0 + (i & 1);
                    if (col > row) sacc[nt][i] = -INFINITY;
                }
            }
        }

        // online softmax
        float mt0 = -INFINITY, mt1 = -INFINITY;
#pragma unroll
        for (int nt = 0; nt < 8; nt++) {
            mt0 = fmaxf(mt0, fmaxf(sacc[nt][0], sacc[nt][1]));
            mt1 = fmaxf(mt1, fmaxf(sacc[nt][2], sacc[nt][3]));
        }
        mt0 = fmaxf(mt0, __shfl_xor_sync(0xffffffffu, mt0, 1));
        mt0 = fmaxf(mt0, __shfl_xor_sync(0xffffffffu, mt0, 2));
        mt1 = fmaxf(mt1, __shfl_xor_sync(0xffffffffu, mt1, 1));
        mt1 = fmaxf(mt1, __shfl_xor_sync(0xffffffffu, mt1, 2));

        const float mn0 = fmaxf(m0, mt0), mn1 = fmaxf(m1, mt1);
        const float cor0 = __expf(m0 - mn0), cor1 = __expf(m1 - mn1);
        m0 = mn0; m1 = mn1;

        float rs0 = 0.f, rs1 = 0.f;
#pragma unroll
        for (int nt = 0; nt < 8; nt++) {
            const float p00 = __expf(sacc[nt][0] - m0);
            const float p01 = __expf(sacc[nt][1] - m0);
            const float p10 = __expf(sacc[nt][2] - m1);
            const float p11 = __expf(sacc[nt][3] - m1);
            rs0 += p00 + p01; rs1 += p10 + p11;
            sacc[nt][0] = p00; sacc[nt][1] = p01;
            sacc[nt][2] = p10; sacc[nt][3] = p11;
        }
        rs0 += __shfl_xor_sync(0xffffffffu, rs0, 1);
        rs0 += __shfl_xor_sync(0xffffffffu, rs0, 2);
        rs1 += __shfl_xor_sync(0xffffffffu, rs1, 1);
        rs1 += __shfl_xor_sync(0xffffffffu, rs1, 2);
        l0 = l0 * cor0 + rs0;
        l1 = l1 * cor1 + rs1;
#pragma unroll
        for (int dt = 0; dt < 8; dt++) {
            oacc[dt][0] *= cor0; oacc[dt][1] *= cor0;
            oacc[dt][2] *= cor1; oacc[dt][3] *= cor1;
        }

        // O += P @ V
#pragma unroll
        for (int kt2 = 0; kt2 < 4; kt2++) {
            uint32_t pa[4];
            pa[0] = pack_h2(sacc[2 * kt2][0],     sacc[2 * kt2][1]);
            pa[1] = pack_h2(sacc[2 * kt2][2],     sacc[2 * kt2][3]);
            pa[2] = pack_h2(sacc[2 * kt2 + 1][0], sacc[2 * kt2 + 1][1]);
            pa[3] = pack_h2(sacc[2 * kt2 + 1][2], sacc[2 * kt2 + 1][3]);
#pragma unroll
            for (int pd = 0; pd < 4; pd++) {
                uint32_t r4[4];
                ldsm4t(r4, vf + (uint32_t)(kt2 * 16 * FSTR + pd * 16) * 2u);
                uint32_t vb0[2] = { r4[0], r4[1] };
                uint32_t vb1[2] = { r4[2], r4[3] };
                mma_f16(oacc[2 * pd],     pa, vb0);
                mma_f16(oacc[2 * pd + 1], pa, vb1);
            }
        }
        if (++buf == 3) buf = 0;
        if (++pbuf == 3) pbuf = 0;
    }

    // write back into [B, L, D_MODEL] as fp16
    const int b = bh >> 4, h = bh & 15;
    const float inv0 = 1.f / l0, inv1 = 1.f / l1;
#pragma unroll
    for (int dt = 0; dt < 8; dt++) {
        const int col = h * DH + dt * 8 + 2 * t;
        __half* o0 = &O[(size_t)(b * SEQ + qr)     * D_MODEL + col];
        __half* o1 = &O[(size_t)(b * SEQ + qr + 8) * D_MODEL + col];
        *(uint32_t*)o0 = pack_h2(oacc[dt][0] * inv0, oacc[dt][1] * inv0);
        *(uint32_t*)o1 = pack_h2(oacc[dt][2] * inv1, oacc[dt][3] * inv1);
    }
}

// ---------------- launch ----------------
extern "C" void kernel_launch(void* const* d_in, const int* in_sizes, int n_in,
                              void* d_out, int out_size)
{
    const float* q  = (const float*)d_in[0];
    const float* k  = (const float*)d_in[1];
    const float* v  = (const float*)d_in[2];
    const float* Wq = (const float*)d_in[3];
    const float* bq = (const float*)d_in[4];
    const float* Wk = (const float*)d_in[5];
    const float* bk = (const float*)d_in[6];
    const float* Wv = (const float*)d_in[7];
    const float* bv = (const float*)d_in[8];
    const float* Wo = (const float*)d_in[9];
    const float* bo = (const float*)d_in[10];
    float* out = (float*)d_out;

    __half *qh, *kh, *vh, *att, *qc, *kc, *vc, *Wt;
    cudaGetSymbolAddress((void**)&qh,  g_qh);
    cudaGetSymbolAddress((void**)&kh,  g_kh);
    cudaGetSymbolAddress((void**)&vh,  g_vh);
    cudaGetSymbolAddress((void**)&att, g_att);
    cudaGetSymbolAddress((void**)&qc,  g_qc);
    cudaGetSymbolAddress((void**)&kc,  g_kc);
    cudaGetSymbolAddress((void**)&vc,  g_vc);
    cudaGetSymbolAddress((void**)&Wt,  g_Wt);

    tohalf3<<<dim3(M_TOTAL * D_MODEL / (256 * 4), 1, 3), 256>>>(q, k, v, qc, kc, vc);
    transpose_half4<<<dim3(32, 32, 4), 256>>>(Wq, Wk, Wv, Wo, Wt);

    cudaFuncSetAttribute(gemm_fp16<1>,
                         cudaFuncAttributeMaxDynamicSharedMemorySize, GEMM_SMEM_B);
    cudaFuncSetAttribute(gemm_fp16<0>,
                         cudaFuncAttributeMaxDynamicSharedMemorySize, GEMM_SMEM_B);
    cudaFuncSetAttribute(flash_fp16,
                         cudaFuncAttributeMaxDynamicSharedMemorySize, FLASH_SMEM_B);

    const size_t WSZ = (size_t)D_MODEL * D_MODEL;
    gemm_fp16<1><<<dim3(D_MODEL / 256, M_TOTAL / 128, 3), 256, GEMM_SMEM_B>>>(
        qc, kc, vc, Wt, Wt + WSZ, Wt + 2 * WSZ, bq, bk, bv, qh, kh, vh);

    flash_fp16<<<dim3(SEQ / 128, BATCH * HEADS), 256, FLASH_SMEM_B>>>(qh, kh, vh, att);

    gemm_fp16<0><<<dim3(D_MODEL / 256, M_TOTAL / 128, 1), 256, GEMM_SMEM_B>>>(
        att, att, att, Wt + 3 * WSZ, Wt + 3 * WSZ, Wt + 3 * WSZ,
        bo, bo, bo, out, out, out);
}

// round 13
// speedup vs baseline: 1.1146x; 1.1146x over previous
#include <cuda_runtime.h>
#include <cuda_fp16.h>
#include <math.h>
#include <stdint.h>

#define D_MODEL 1024
#define HEADS   16
#define DH      64
#define BATCH   4
#define SEQ     2048
#define M_TOTAL (BATCH * SEQ)   // 8192

// ---------------- scratch (device globals: allocation-guard safe) ----------------
__device__ __half g_qh[(size_t)BATCH * HEADS * SEQ * DH];   // [B,H,L,Dh] fp16 (q pre-scaled)
__device__ __half g_kh[(size_t)BATCH * HEADS * SEQ * DH];
__device__ __half g_vh[(size_t)BATCH * HEADS * SEQ * DH];
__device__ __half g_att[(size_t)M_TOTAL * D_MODEL];         // [B*L, D_MODEL] fp16
__device__ __half g_qc[(size_t)M_TOTAL * D_MODEL];          // fp16 inputs
__device__ __half g_kc[(size_t)M_TOTAL * D_MODEL];
__device__ __half g_vc[(size_t)M_TOTAL * D_MODEL];
__device__ __half g_Wt[(size_t)4 * D_MODEL * D_MODEL];      // fp16, transposed [n][k]

// ---------------- helpers ----------------
__device__ __forceinline__ uint32_t smem_u32(const void* p) {
    uint32_t a;
    asm("{ .reg .u64 t; cvta.to.shared.u64 t, %1; cvt.u32.u64 %0, t; }" : "=r"(a) : "l"(p));
    return a;
}

__device__ __forceinline__ uint32_t pack_h2(float lo, float hi) {
    uint32_t r;
    asm("cvt.rn.f16x2.f32 %0, %1, %2;" : "=r"(r) : "f"(hi), "f"(lo));
    return r;
}

__device__ __forceinline__ void mma_f16(float c[4], const uint32_t a[4], const uint32_t b[2]) {
    asm("mma.sync.aligned.m16n8k16.row.col.f32.f16.f16.f32 "
        "{%0,%1,%2,%3}, {%4,%5,%6,%7}, {%8,%9}, {%0,%1,%2,%3};"
        : "+f"(c[0]), "+f"(c[1]), "+f"(c[2]), "+f"(c[3])
        : "r"(a[0]), "r"(a[1]), "r"(a[2]), "r"(a[3]), "r"(b[0]), "r"(b[1]));
}

__device__ __forceinline__ void ldsm4(uint32_t r[4], uint32_t saddr) {
    asm volatile("ldmatrix.sync.aligned.m8n8.x4.shared.b16 {%0,%1,%2,%3}, [%4];"
        : "=r"(r[0]), "=r"(r[1]), "=r"(r[2]), "=r"(r[3]) : "r"(saddr));
}

__device__ __forceinline__ void ldsm4t(uint32_t r[4], uint32_t saddr) {
    asm volatile("ldmatrix.sync.aligned.m8n8.x4.trans.shared.b16 {%0,%1,%2,%3}, [%4];"
        : "=r"(r[0]), "=r"(r[1]), "=r"(r[2]), "=r"(r[3]) : "r"(saddr));
}

#define CPA16(dst, src) asm volatile("cp.async.cg.shared.global [%0], [%1], 16;" :: "r"(dst), "l"(src))
#define CPA_COMMIT()    asm volatile("cp.async.commit_group;")
#define CPA_WAIT1()     asm volatile("cp.async.wait_group 1;")
#define CPA_WAIT0()     asm volatile("cp.async.wait_group 0;")

// swizzled offset within a 128B-row region: row*128 + ((chunk ^ (row&7)) << 4)
#define SWZ(row, chunk) ((uint32_t)(((row) << 7) + ((((chunk) ^ ((row) & 7))) << 4)))

// ---------------- prologue converts ----------------
__global__ __launch_bounds__(256) void tohalf3(
    const float* __restrict__ a, const float* __restrict__ b, const float* __restrict__ c,
    __half* __restrict__ oa, __half* __restrict__ ob, __half* __restrict__ oc)
{
    const int z = blockIdx.z;
    const float* in = (z == 0) ? a : (z == 1) ? b : c;
    __half* out     = (z == 0) ? oa : (z == 1) ? ob : oc;
    const size_t i = ((size_t)blockIdx.x * 256 + threadIdx.x) * 4;
    float4 v = *(const float4*)(in + i);
    uint2 u = { pack_h2(v.x, v.y), pack_h2(v.z, v.w) };
    *(uint2*)(out + i) = u;
}

__global__ __launch_bounds__(256) void transpose_half4(
    const float* __restrict__ w0, const float* __restrict__ w1,
    const float* __restrict__ w2, const float* __restrict__ w3,
    __half* __restrict__ outbase)
{
    const int z = blockIdx.z;
    const float* in = (z == 0) ? w0 : (z == 1) ? w1 : (z == 2) ? w2 : w3;
    __half* out = outbase + (size_t)z * D_MODEL * D_MODEL;

    __shared__ float tile[32][33];
    const int tx = threadIdx.x & 31, ty = threadIdx.x >> 5;   // 32x8
    const int x = blockIdx.x * 32 + tx;
    const int y = blockIdx.y * 32 + ty;
#pragma unroll
    for (int j = 0; j < 32; j += 8)
        tile[ty + j][tx] = in[(size_t)(y + j) * D_MODEL + x];   // in[k][n]
    __syncthreads();
    const int x2 = blockIdx.y * 32 + tx;
    const int y2 = blockIdx.x * 32 + ty;
#pragma unroll
    for (int j = 0; j < 32; j += 8)
        out[(size_t)(y2 + j) * D_MODEL + x2] = __float2half_rn(tile[tx][ty + j]);  // out[n][k]
}

// ---------------- FP16 GEMM: CTA 128x256, warp 64x64, 3-stage cp.async, SW128 ----------------
#define ABYTES (128 * 128)              // A stage: 128 rows x 128B
#define BBYTES (256 * 128)              // B stage: 256 rows x 128B
#define STAGE_B (ABYTES + BBYTES)       // 49152
#define GEMM_SMEM_B (3 * STAGE_B)       // 147456

template <int HEADSPLIT>
__global__ __launch_bounds__(256) void gemm_fp16(
    const __half* __restrict__ A0, const __half* __restrict__ A1, const __half* __restrict__ A2,
    const __half* __restrict__ T0, const __half* __restrict__ T1, const __half* __restrict__ T2,
    const float* __restrict__ b0, const float* __restrict__ b1, const float* __restrict__ b2,
    void* __restrict__ C0, void* __restrict__ C1, void* __restrict__ C2)
{
    const int z = blockIdx.z;
    const __half* A   = (z == 0) ? A0 : (z == 1) ? A1 : A2;
    const __half* Wt  = (z == 0) ? T0 : (z == 1) ? T1 : T2;
    const float* bias = (z == 0) ? b0 : (z == 1) ? b1 : b2;
    void* C           = (z == 0) ? C0 : (z == 1) ? C1 : C2;
    const float oscale = (HEADSPLIT && z == 0) ? 0.125f : 1.0f;   // fold 1/sqrt(Dh) into q

    extern __shared__ __half sh[];
    const uint32_t sbase = smem_u32(sh);
    const int tid = threadIdx.x;
    const int lane = tid & 31;
    const int w = tid >> 5;
    const int g = lane >> 2, t = lane & 3;
    const int wm = w >> 2, wn = w & 3;           // 2 x 4 warps -> 64x64 tiles
    const int bm = blockIdx.y * 128, bn = blockIdx.x * 256;

    float acc[4][8][4];
#pragma unroll
    for (int mt = 0; mt < 4; mt++)
#pragma unroll
        for (int nt = 0; nt < 8; nt++)
#pragma unroll
            for (int i = 0; i < 4; i++) acc[mt][nt][i] = 0.f;

    // cp.async staging: thread -> row tid>>1, chunk base (tid&1)*4, 4 x 16B per matrix row
    const int srow = tid >> 1;
    const int cb = (tid & 1) * 4;
    const int sxr = srow & 7;
    const __half* Ag  = A  + (size_t)(bm + srow) * D_MODEL + (tid & 1) * 32;
    const __half* Bg0 = Wt + (size_t)(bn + srow) * D_MODEL + (tid & 1) * 32;
    const __half* Bg1 = Bg0 + (size_t)128 * D_MODEL;
    uint32_t adst[4], bdst0[4], bdst1[4];
#pragma unroll
    for (int j = 0; j < 4; j++) {
        const uint32_t swc = (uint32_t)(((cb + j) ^ sxr) << 4);
        adst[j]  = sbase + (uint32_t)(srow << 7) + swc;
        bdst0[j] = sbase + ABYTES + (uint32_t)(srow << 7) + swc;
        bdst1[j] = bdst0[j] + (uint32_t)(128 << 7);
    }

    // prologue: tiles 0,1 -> stages 0,1
#pragma unroll
    for (int p = 0; p < 2; p++) {
        const int k0 = p * 64;
        const uint32_t so = (uint32_t)(p * STAGE_B);
#pragma unroll
        for (int j = 0; j < 4; j++) CPA16(adst[j] + so, Ag + k0 + j * 8);
#pragma unroll
        for (int j = 0; j < 4; j++) CPA16(bdst0[j] + so, Bg0 + k0 + j * 8);
#pragma unroll
        for (int j = 0; j < 4; j++) CPA16(bdst1[j] + so, Bg1 + k0 + j * 8);
        CPA_COMMIT();
    }

    // fragment bases
    const int lrow = (lane & 7) + ((lane >> 3) & 1) * 8;
    const int hi = lane >> 4;                   // 0/1
    const int bhi = (lane >> 3) & 1;            // 0/1
    const int bn_lane = (lane & 7) + hi * 8;
    const int xa = lrow & 7;
    const int xb = bn_lane & 7;
    uint32_t a_base[4], b_base[4];
#pragma unroll
    for (int mt = 0; mt < 4; mt++)
        a_base[mt] = sbase + (uint32_t)((wm * 64 + mt * 16 + lrow) << 7);
#pragma unroll
    for (int p = 0; p < 4; p++)
        b_base[p] = sbase + ABYTES + (uint32_t)((wn * 64 + p * 16 + bn_lane) << 7);

    int s = 0, s2 = 2;
    for (int i = 0; i < 16; i++) {
        if (i + 1 < 16) { CPA_WAIT1(); } else { CPA_WAIT0(); }
        __syncthreads();
        if (i + 2 < 16) {
            const int k0 = (i + 2) * 64;
            const uint32_t so = (uint32_t)(s2 * STAGE_B);
#pragma unroll
            for (int j = 0; j < 4; j++) CPA16(adst[j] + so, Ag + k0 + j * 8);
#pragma unroll
            for (int j = 0; j < 4; j++) CPA16(bdst0[j] + so, Bg0 + k0 + j * 8);
#pragma unroll
            for (int j = 0; j < 4; j++) CPA16(bdst1[j] + so, Bg1 + k0 + j * 8);
            CPA_COMMIT();
        }
        const uint32_t so = (uint32_t)(s * STAGE_B);
#pragma unroll
        for (int ks = 0; ks < 4; ks++) {
            const uint32_t ca = (uint32_t)((((ks << 1) + hi) ^ xa) << 4);
            const uint32_t cbk = (uint32_t)((((ks << 1) + bhi) ^ xb) << 4);
            uint32_t a[4][4], b[8][2];
#pragma unroll
            for (int mt = 0; mt < 4; mt++)
                ldsm4(a[mt], a_base[mt] + so + ca);
#pragma unroll
            for (int p = 0; p < 4; p++) {
                uint32_t r4[4];
                ldsm4(r4, b_base[p] + so + cbk);
                b[2 * p][0] = r4[0];     b[2 * p][1] = r4[1];
                b[2 * p + 1][0] = r4[2]; b[2 * p + 1][1] = r4[3];
            }
#pragma unroll
            for (int mt = 0; mt < 4; mt++)
#pragma unroll
                for (int nt = 0; nt < 8; nt++)
                    mma_f16(acc[mt][nt], a[mt], b[nt]);
        }
        if (++s == 3) s = 0;
        if (++s2 == 3) s2 = 0;
    }

    // epilogue
#pragma unroll
    for (int mt = 0; mt < 4; mt++) {
#pragma unroll
        for (int nt = 0; nt < 8; nt++) {
            const int r0 = bm + wm * 64 + mt * 16 + g;
            const int c0 = bn + wn * 64 + nt * 8 + 2 * t;
#pragma unroll
            for (int i = 0; i < 4; i++) {
                const int row = r0 + (i >> 1) * 8;
                const int col = c0 + (i & 1);
                const float v = (acc[mt][nt][i] + bias[col]) * oscale;
                if (HEADSPLIT) {
                    const int b = row >> 11, l = row & (SEQ - 1);
                    const int h = col >> 6,  d = col & 63;
                    ((__half*)C)[(((size_t)(b * HEADS + h) * SEQ + l) << 6) + d] =
                        __float2half_rn(v);
                } else {
                    ((float*)C)[(size_t)row * D_MODEL + col] = v;
                }
            }
        }
    }
}

// ---------------- FP16 flash attention: 3-buffer cp.async, SW128, ldsm Q/K, ldsm.trans V ----------------
// BQ=128, BK=64, 256 threads, warp = 16 q-rows. Q arrives pre-scaled by 0.125.
#define QBYTES (128 * 128)               // 16384
#define KBYTES (64 * 128)                // 8192
#define KVBUF_B (2 * KBYTES)             // K then V per buffer
#define FLASH_SMEM_B (QBYTES + 3 * KVBUF_B)  // 65536

__global__ __launch_bounds__(256) void flash_fp16(
    const __half* __restrict__ Q, const __half* __restrict__ K,
    const __half* __restrict__ V, __half* __restrict__ O)
{
    extern __shared__ __half sm[];
    const uint32_t sbase = smem_u32(sm);
    const uint32_t kvbase = sbase + QBYTES;

    const int tid = threadIdx.x;
    const int lane = tid & 31;
    const int w = tid >> 5;
    const int g = lane >> 2, t = lane & 3;
    const int bh = blockIdx.y;
    const int bx = blockIdx.x;
    const int q0 = bx * 128;

    const __half* Qb = Q + (size_t)bh * SEQ * DH;
    const __half* Kb = K + (size_t)bh * SEQ * DH;
    const __half* Vb = V + (size_t)bh * SEQ * DH;

    // staging maps
    const int qrow = tid >> 1, qcb = (tid & 1) * 4;
    const int krow = tid >> 2, kcb = (tid & 3) * 2;
    const __half* Qg = Qb + (size_t)(q0 + qrow) * DH + (tid & 1) * 32;
    const __half* Kg = Kb + (size_t)krow * DH + (tid & 3) * 16;
    const __half* Vg = Vb + (size_t)krow * DH + (tid & 3) * 16;
    uint32_t qdst[4], kdst[2], vdst[2];
#pragma unroll
    for (int j = 0; j < 4; j++)
        qdst[j] = sbase + SWZ(qrow, qcb + j);
#pragma unroll
    for (int j = 0; j < 2; j++) {
        kdst[j] = kvbase + SWZ(krow, kcb + j);
        vdst[j] = kdst[j] + (uint32_t)KBYTES;
    }

    const int jmax = 2 * bx + 1;

    // prologue: group0 = Q + KV tile0, group1 = KV tile1
#pragma unroll
    for (int j = 0; j < 4; j++) CPA16(qdst[j], Qg + j * 8);
#pragma unroll
    for (int j = 0; j < 2; j++) CPA16(kdst[j], Kg + j * 8);
#pragma unroll
    for (int j = 0; j < 2; j++) CPA16(vdst[j], Vg + j * 8);
    CPA_COMMIT();
    {
        const size_t koffg = (size_t)64 * DH;
#pragma unroll
        for (int j = 0; j < 2; j++) CPA16(kdst[j] + KVBUF_B, Kg + koffg + j * 8);
#pragma unroll
        for (int j = 0; j < 2; j++) CPA16(vdst[j] + KVBUF_B, Vg + koffg + j * 8);
        CPA_COMMIT();
    }

    // fragment bases
    const int lrow = (lane & 7) + ((lane >> 3) & 1) * 8;
    const int hi = lane >> 4;
    const int bhi = (lane >> 3) & 1;
    const int bn_lane = (lane & 7) + hi * 8;
    const int xq = lrow & 7;
    const int xk = bn_lane & 7;
    const uint32_t q_base = sbase + (uint32_t)((w * 16 + lrow) << 7);
    uint32_t k_base[4], v_base[4];
#pragma unroll
    for (int p = 0; p < 4; p++) {
        k_base[p] = kvbase + (uint32_t)((p * 16 + bn_lane) << 7);
        v_base[p] = kvbase + KBYTES + (uint32_t)((p * 16 + lrow) << 7);
    }

    float oacc[8][4];
#pragma unroll
    for (int dt = 0; dt < 8; dt++)
#pragma unroll
        for (int i = 0; i < 4; i++) oacc[dt][i] = 0.f;
    float m0 = -INFINITY, m1 = -INFINITY, l0 = 0.f, l1 = 0.f;

    const int qr = q0 + w * 16 + g;

    int buf = 0, pbuf = 2;
    for (int j = 0; j <= jmax; j++) {
        if (j + 1 <= jmax) { CPA_WAIT1(); } else { CPA_WAIT0(); }
        __syncthreads();
        if (j + 2 <= jmax) {
            const size_t koffg = (size_t)(j + 2) * 64 * DH;
            const uint32_t bo = (uint32_t)(pbuf * KVBUF_B);
#pragma unroll
            for (int jj = 0; jj < 2; jj++) CPA16(kdst[jj] + bo, Kg + koffg + jj * 8);
#pragma unroll
            for (int jj = 0; jj < 2; jj++) CPA16(vdst[jj] + bo, Vg + koffg + jj * 8);
            CPA_COMMIT();
        }
        const uint32_t bo = (uint32_t)(buf * KVBUF_B);
        const int k0 = j * 64;

        // S = Q K^T (Q pre-scaled)
        float sacc[8][4];
#pragma unroll
        for (int nt = 0; nt < 8; nt++)
#pragma unroll
            for (int i = 0; i < 4; i++) sacc[nt][i] = 0.f;
#pragma unroll
        for (int kt = 0; kt < 4; kt++) {
            const uint32_t cq = (uint32_t)((((kt << 1) + hi) ^ xq) << 4);
            const uint32_t ck = (uint32_t)((((kt << 1) + bhi) ^ xk) << 4);
            uint32_t qf[4];
            ldsm4(qf, q_base + cq);
            uint32_t kb[8][2];
#pragma unroll
            for (int p = 0; p < 4; p++) {
                uint32_t r4[4];
                ldsm4(r4, k_base[p] + bo + ck);
                kb[2 * p][0] = r4[0];     kb[2 * p][1] = r4[1];
                kb[2 * p + 1][0] = r4[2]; kb[2 * p + 1][1] = r4[3];
            }
#pragma unroll
            for (int nt = 0; nt < 8; nt++)
                mma_f16(sacc[nt], qf, kb[nt]);
        }

        // causal mask: only on the two diagonal-adjacent tiles
        if (j >= 2 * bx) {
#pragma unroll
            for (int nt = 0; nt < 8; nt++) {
                const int c0 = k0 + nt * 8 + 2 * t;
#pragma unroll
                for (int i = 0; i < 4; i++) {
                    const int row = (i >> 1) ? qr + 8 : qr;
                    const int col = c0 + (i & 1);
                    if (col > row) sacc[nt][i] = -INFINITY;
                }
            }
        }

        // online softmax
        float mt0 = -INFINITY, mt1 = -INFINITY;
#pragma unroll
        for (int nt = 0; nt < 8; nt++) {
            mt0 = fmaxf(mt0, fmaxf(sacc[nt][0], sacc[nt][1]));
            mt1 = fmaxf(mt1, fmaxf(sacc[nt][2], sacc[nt][3]));
        }
        mt0 = fmaxf(mt0, __shfl_xor_sync(0xffffffffu, mt0, 1));
        mt0 = fmaxf(mt0, __shfl_xor_sync(0xffffffffu, mt0, 2));
        mt1 = fmaxf(mt1, __shfl_xor_sync(0xffffffffu, mt1, 1));
        mt1 = fmaxf(mt1, __shfl_xor_sync(0xffffffffu, mt1, 2));

        const float mn0 = fmaxf(m0, mt0), mn1 = fmaxf(m1, mt1);
        const float cor0 = __expf(m0 - mn0), cor1 = __expf(m1 - mn1);
        m0 = mn0; m1 = mn1;

        float rs0 = 0.f, rs1 = 0.f;
#pragma unroll
        for (int nt = 0; nt < 8; nt++) {
            const float p00 = __expf(sacc[nt][0] - m0);
            const float p01 = __expf(sacc[nt][1] - m0);
            const float p10 = __expf(sacc[nt][2] - m1);
            const float p11 = __expf(sacc[nt][3] - m1);
            rs0 += p00 + p01; rs1 += p10 + p11;
            sacc[nt][0] = p00; sacc[nt][1] = p01;
            sacc[nt][2] = p10; sacc[nt][3] = p11;
        }
        rs0 += __shfl_xor_sync(0xffffffffu, rs0, 1);
        rs0 += __shfl_xor_sync(0xffffffffu, rs0, 2);
        rs1 += __shfl_xor_sync(0xffffffffu, rs1, 1);
        rs1 += __shfl_xor_sync(0xffffffffu, rs1, 2);
        l0 = l0 * cor0 + rs0;
        l1 = l1 * cor1 + rs1;
        // rescale O only when the running max actually changed (cor==1.0f is exact identity)
        if (cor0 != 1.0f) {
#pragma unroll
            for (int dt = 0; dt < 8; dt++) { oacc[dt][0] *= cor0; oacc[dt][1] *= cor0; }
        }
        if (cor1 != 1.0f) {
#pragma unroll
            for (int dt = 0; dt < 8; dt++) { oacc[dt][2] *= cor1; oacc[dt][3] *= cor1; }
        }

        // O += P @ V
#pragma unroll
        for (int kt2 = 0; kt2 < 4; kt2++) {
            uint32_t pa[4];
            pa[0] = pack_h2(sacc[2 * kt2][0],     sacc[2 * kt2][1]);
            pa[1] = pack_h2(sacc[2 * kt2][2],     sacc[2 * kt2][3]);
            pa[2] = pack_h2(sacc[2 * kt2 + 1][0], sacc[2 * kt2 + 1][1]);
            pa[3] = pack_h2(sacc[2 * kt2 + 1][2], sacc[2 * kt2 + 1][3]);
#pragma unroll
            for (int pd = 0; pd < 4; pd++) {
                const uint32_t cv = (uint32_t)((((pd << 1) + hi) ^ xq) << 4);
                uint32_t r4[4];
                ldsm4t(r4, v_base[kt2] + bo + cv);
                uint32_t vb0[2] = { r4[0], r4[1] };
                uint32_t vb1[2] = { r4[2], r4[3] };
                mma_f16(oacc[2 * pd],     pa, vb0);
                mma_f16(oacc[2 * pd + 1], pa, vb1);
            }
        }
        if (++buf == 3) buf = 0;
        if (++pbuf == 3) pbuf = 0;
    }

    // write back into [B, L, D_MODEL] as fp16
    const int b = bh >> 4, h = bh & 15;
    const float inv0 = 1.f / l0, inv1 = 1.f / l1;
#pragma unroll
    for (int dt = 0; dt < 8; dt++) {
        const int col = h * DH + dt * 8 + 2 * t;
        __half* o0 = &O[(size_t)(b * SEQ + qr)     * D_MODEL + col];
        __half* o1 = &O[(size_t)(b * SEQ + qr + 8) * D_MODEL + col];
        *(uint32_t*)o0 = pack_h2(oacc[dt][0] * inv0, oacc[dt][1] * inv0);
        *(uint32_t*)o1 = pack_h2(oacc[dt][2] * inv1, oacc[dt][3] * inv1);
    }
}

// ---------------- launch ----------------
extern "C" void kernel_launch(void* const* d_in, const int* in_sizes, int n_in,
                              void* d_out, int out_size)
{
    const float* q  = (const float*)d_in[0];
    const float* k  = (const float*)d_in[1];
    const float* v  = (const float*)d_in[2];
    const float* Wq = (const float*)d_in[3];
    const float* bq = (const float*)d_in[4];
    const float* Wk = (const float*)d_in[5];
    const float* bk = (const float*)d_in[6];
    const float* Wv = (const float*)d_in[7];
    const float* bv = (const float*)d_in[8];
    const float* Wo = (const float*)d_in[9];
    const float* bo = (const float*)d_in[10];
    float* out = (float*)d_out;

    __half *qh, *kh, *vh, *att, *qc, *kc, *vc, *Wt;
    cudaGetSymbolAddress((void**)&qh,  g_qh);
    cudaGetSymbolAddress((void**)&kh,  g_kh);
    cudaGetSymbolAddress((void**)&vh,  g_vh);
    cudaGetSymbolAddress((void**)&att, g_att);
    cudaGetSymbolAddress((void**)&qc,  g_qc);
    cudaGetSymbolAddress((void**)&kc,  g_kc);
    cudaGetSymbolAddress((void**)&vc,  g_vc);
    cudaGetSymbolAddress((void**)&Wt,  g_Wt);

    tohalf3<<<dim3(M_TOTAL * D_MODEL / (256 * 4), 1, 3), 256>>>(q, k, v, qc, kc, vc);
    transpose_half4<<<dim3(32, 32, 4), 256>>>(Wq, Wk, Wv, Wo, Wt);

    cudaFuncSetAttribute(gemm_fp16<1>,
                         cudaFuncAttributeMaxDynamicSharedMemorySize, GEMM_SMEM_B);
    cudaFuncSetAttribute(gemm_fp16<0>,
                         cudaFuncAttributeMaxDynamicSharedMemorySize, GEMM_SMEM_B);
    cudaFuncSetAttribute(flash_fp16,
                         cudaFuncAttributeMaxDynamicSharedMemorySize, FLASH_SMEM_B);

    const size_t WSZ = (size_t)D_MODEL * D_MODEL;
    gemm_fp16<1><<<dim3(D_MODEL / 256, M_TOTAL / 128, 3), 256, GEMM_SMEM_B>>>(
        qc, kc, vc, Wt, Wt + WSZ, Wt + 2 * WSZ, bq, bk, bv, qh, kh, vh);

    flash_fp16<<<dim3(SEQ / 128, BATCH * HEADS), 256, FLASH_SMEM_B>>>(qh, kh, vh, att);

    gemm_fp16<0><<<dim3(D_MODEL / 256, M_TOTAL / 128, 1), 256, GEMM_SMEM_B>>>(
        att, att, att, Wt + 3 * WSZ, Wt + 3 * WSZ, Wt + 3 * WSZ,
        bo, bo, bo, out, out, out);
}

// round 14
// speedup vs baseline: 1.2817x; 1.1499x over previous
#include <cuda_runtime.h>
#include <cuda_fp16.h>
#include <math.h>
#include <stdint.h>

#define D_MODEL 1024
#define HEADS   16
#define DH      64
#define BATCH   4
#define SEQ     2048
#define M_TOTAL (BATCH * SEQ)   // 8192
#define LOG2E   1.44269504088896340736f

// ---------------- scratch (device globals: allocation-guard safe) ----------------
__device__ __half g_qh[(size_t)BATCH * HEADS * SEQ * DH];   // q pre-scaled by 0.125*log2e
__device__ __half g_kh[(size_t)BATCH * HEADS * SEQ * DH];
__device__ __half g_vh[(size_t)BATCH * HEADS * SEQ * DH];
__device__ __half g_att[(size_t)M_TOTAL * D_MODEL];
__device__ __half g_qc[(size_t)M_TOTAL * D_MODEL];
__device__ __half g_kc[(size_t)M_TOTAL * D_MODEL];
__device__ __half g_vc[(size_t)M_TOTAL * D_MODEL];
__device__ __half g_Wt[(size_t)4 * D_MODEL * D_MODEL];      // fp16, transposed [n][k]

// ---------------- helpers ----------------
__device__ __forceinline__ uint32_t smem_u32(const void* p) {
    uint32_t a;
    asm("{ .reg .u64 t; cvta.to.shared.u64 t, %1; cvt.u32.u64 %0, t; }" : "=r"(a) : "l"(p));
    return a;
}

__device__ __forceinline__ uint32_t pack_h2(float lo, float hi) {
    uint32_t r;
    asm("cvt.rn.f16x2.f32 %0, %1, %2;" : "=r"(r) : "f"(hi), "f"(lo));
    return r;
}

__device__ __forceinline__ void mma_f16(float c[4], const uint32_t a[4], const uint32_t b[2]) {
    asm("mma.sync.aligned.m16n8k16.row.col.f32.f16.f16.f32 "
        "{%0,%1,%2,%3}, {%4,%5,%6,%7}, {%8,%9}, {%0,%1,%2,%3};"
        : "+f"(c[0]), "+f"(c[1]), "+f"(c[2]), "+f"(c[3])
        : "r"(a[0]), "r"(a[1]), "r"(a[2]), "r"(a[3]), "r"(b[0]), "r"(b[1]));
}

__device__ __forceinline__ void ldsm4(uint32_t r[4], uint32_t saddr) {
    asm volatile("ldmatrix.sync.aligned.m8n8.x4.shared.b16 {%0,%1,%2,%3}, [%4];"
        : "=r"(r[0]), "=r"(r[1]), "=r"(r[2]), "=r"(r[3]) : "r"(saddr));
}

__device__ __forceinline__ void ldsm4t(uint32_t r[4], uint32_t saddr) {
    asm volatile("ldmatrix.sync.aligned.m8n8.x4.trans.shared.b16 {%0,%1,%2,%3}, [%4];"
        : "=r"(r[0]), "=r"(r[1]), "=r"(r[2]), "=r"(r[3]) : "r"(saddr));
}

#define CPA16(dst, src) asm volatile("cp.async.cg.shared.global [%0], [%1], 16;" :: "r"(dst), "l"(src))
#define CPA_COMMIT()    asm volatile("cp.async.commit_group;")
#define CPA_WAIT1()     asm volatile("cp.async.wait_group 1;")
#define CPA_WAIT0()     asm volatile("cp.async.wait_group 0;")

#define SWZ(row, chunk) ((uint32_t)(((row) << 7) + ((((chunk) ^ ((row) & 7))) << 4)))

// ---------------- prologue converts ----------------
__global__ __launch_bounds__(256) void tohalf3(
    const float* __restrict__ a, const float* __restrict__ b, const float* __restrict__ c,
    __half* __restrict__ oa, __half* __restrict__ ob, __half* __restrict__ oc)
{
    const int z = blockIdx.z;
    const float* in = (z == 0) ? a : (z == 1) ? b : c;
    __half* out     = (z == 0) ? oa : (z == 1) ? ob : oc;
    const size_t i = ((size_t)blockIdx.x * 256 + threadIdx.x) * 4;
    float4 v = *(const float4*)(in + i);
    uint2 u = { pack_h2(v.x, v.y), pack_h2(v.z, v.w) };
    *(uint2*)(out + i) = u;
}

__global__ __launch_bounds__(256) void transpose_half4(
    const float* __restrict__ w0, const float* __restrict__ w1,
    const float* __restrict__ w2, const float* __restrict__ w3,
    __half* __restrict__ outbase)
{
    const int z = blockIdx.z;
    const float* in = (z == 0) ? w0 : (z == 1) ? w1 : (z == 2) ? w2 : w3;
    __half* out = outbase + (size_t)z * D_MODEL * D_MODEL;

    __shared__ float tile[32][33];
    const int tx = threadIdx.x & 31, ty = threadIdx.x >> 5;
    const int x = blockIdx.x * 32 + tx;
    const int y = blockIdx.y * 32 + ty;
#pragma unroll
    for (int j = 0; j < 32; j += 8)
        tile[ty + j][tx] = in[(size_t)(y + j) * D_MODEL + x];
    __syncthreads();
    const int x2 = blockIdx.y * 32 + tx;
    const int y2 = blockIdx.x * 32 + ty;
#pragma unroll
    for (int j = 0; j < 32; j += 8)
        out[(size_t)(y2 + j) * D_MODEL + x2] = __float2half_rn(tile[tx][ty + j]);
}

// ---------------- FP16 GEMM: 512 threads, CTA 128x256, warp 64x32, 3-stage, SW128 ----------------
#define ABYTES (128 * 128)
#define BBYTES (256 * 128)
#define STAGE_B (ABYTES + BBYTES)       // 49152
#define GEMM_SMEM_B (3 * STAGE_B)       // 147456

template <int HEADSPLIT>
__global__ __launch_bounds__(512) void gemm_fp16(
    const __half* __restrict__ A0, const __half* __restrict__ A1, const __half* __restrict__ A2,
    const __half* __restrict__ T0, const __half* __restrict__ T1, const __half* __restrict__ T2,
    const float* __restrict__ b0, const float* __restrict__ b1, const float* __restrict__ b2,
    void* __restrict__ C0, void* __restrict__ C1, void* __restrict__ C2)
{
    const int z = blockIdx.z;
    const __half* A   = (z == 0) ? A0 : (z == 1) ? A1 : A2;
    const __half* Wt  = (z == 0) ? T0 : (z == 1) ? T1 : T2;
    const float* bias = (z == 0) ? b0 : (z == 1) ? b1 : b2;
    void* C           = (z == 0) ? C0 : (z == 1) ? C1 : C2;
    // q gets 1/sqrt(Dh) * log2e folded in (flash uses exp2)
    const float oscale = (HEADSPLIT && z == 0) ? (0.125f * LOG2E) : 1.0f;

    extern __shared__ __half sh[];
    const uint32_t sbase = smem_u32(sh);
    const int tid = threadIdx.x;
    const int lane = tid & 31;
    const int w = tid >> 5;                      // 0..15
    const int g = lane >> 2, t = lane & 3;
    const int wm = w >> 3, wn = w & 7;           // warp tile 64x32
    const int bm = blockIdx.y * 128, bn = blockIdx.x * 256;

    float acc[4][4][4];
#pragma unroll
    for (int mt = 0; mt < 4; mt++)
#pragma unroll
        for (int nt = 0; nt < 4; nt++)
#pragma unroll
            for (int i = 0; i < 4; i++) acc[mt][nt][i] = 0.f;

    // staging: A row tid>>2 (2 chunks), B row tid>>1 (4 chunks)
    const int arow = tid >> 2, acb = (tid & 3) * 2;
    const int brow = tid >> 1, bcb = (tid & 1) * 4;
    const __half* Ag = A  + (size_t)(bm + arow) * D_MODEL + (tid & 3) * 16;
    const __half* Bg = Wt + (size_t)(bn + brow) * D_MODEL + (tid & 1) * 32;
    uint32_t adst[2], bdst[4];
#pragma unroll
    for (int j = 0; j < 2; j++)
        adst[j] = sbase + SWZ(arow, acb + j);
#pragma unroll
    for (int j = 0; j < 4; j++)
        bdst[j] = sbase + ABYTES + SWZ(brow, bcb + j);

    // prologue: tiles 0,1 -> stages 0,1
#pragma unroll
    for (int p = 0; p < 2; p++) {
        const int k0 = p * 64;
        const uint32_t so = (uint32_t)(p * STAGE_B);
#pragma unroll
        for (int j = 0; j < 2; j++) CPA16(adst[j] + so, Ag + k0 + j * 8);
#pragma unroll
        for (int j = 0; j < 4; j++) CPA16(bdst[j] + so, Bg + k0 + j * 8);
        CPA_COMMIT();
    }

    // fragment bases
    const int lrow = (lane & 7) + ((lane >> 3) & 1) * 8;
    const int hi = lane >> 4;
    const int bhi = (lane >> 3) & 1;
    const int bn_lane = (lane & 7) + hi * 8;
    const int xa = lrow & 7;
    const int xb = bn_lane & 7;
    uint32_t a_base[4], b_base[2];
#pragma unroll
    for (int mt = 0; mt < 4; mt++)
        a_base[mt] = sbase + (uint32_t)((wm * 64 + mt * 16 + lrow) << 7);
#pragma unroll
    for (int p = 0; p < 2; p++)
        b_base[p] = sbase + ABYTES + (uint32_t)((wn * 32 + p * 16 + bn_lane) << 7);

    int s = 0, s2 = 2;
    for (int i = 0; i < 16; i++) {
        if (i + 1 < 16) { CPA_WAIT1(); } else { CPA_WAIT0(); }
        __syncthreads();
        if (i + 2 < 16) {
            const int k0 = (i + 2) * 64;
            const uint32_t so = (uint32_t)(s2 * STAGE_B);
#pragma unroll
            for (int j = 0; j < 2; j++) CPA16(adst[j] + so, Ag + k0 + j * 8);
#pragma unroll
            for (int j = 0; j < 4; j++) CPA16(bdst[j] + so, Bg + k0 + j * 8);
            CPA_COMMIT();
        }
        const uint32_t so = (uint32_t)(s * STAGE_B);
#pragma unroll
        for (int ks = 0; ks < 4; ks++) {
            const uint32_t ca = (uint32_t)((((ks << 1) + hi) ^ xa) << 4);
            const uint32_t cbk = (uint32_t)((((ks << 1) + bhi) ^ xb) << 4);
            uint32_t a[4][4], b[4][2];
#pragma unroll
            for (int mt = 0; mt < 4; mt++)
                ldsm4(a[mt], a_base[mt] + so + ca);
#pragma unroll
            for (int p = 0; p < 2; p++) {
                uint32_t r4[4];
                ldsm4(r4, b_base[p] + so + cbk);
                b[2 * p][0] = r4[0];     b[2 * p][1] = r4[1];
                b[2 * p + 1][0] = r4[2]; b[2 * p + 1][1] = r4[3];
            }
#pragma unroll
            for (int mt = 0; mt < 4; mt++)
#pragma unroll
                for (int nt = 0; nt < 4; nt++)
                    mma_f16(acc[mt][nt], a[mt], b[nt]);
        }
        if (++s == 3) s = 0;
        if (++s2 == 3) s2 = 0;
    }

    if (HEADSPLIT) {
        // ---- epilogue: smem bounce (64KB half tile, swizzled) -> coalesced 16B STG ----
        __syncthreads();   // all warps done reading stages before overwrite
#pragma unroll
        for (int mt = 0; mt < 4; mt++) {
            const int r0 = wm * 64 + mt * 16 + g;   // local rows r0, r0+8
            const uint32_t sw0 = (uint32_t)(r0 << 9) + (uint32_t)(4 * t);
            const uint32_t sw1 = sw0 + (uint32_t)(8 << 9);
#pragma unroll
            for (int nt = 0; nt < 4; nt++) {
                const int colc = wn * 4 + nt;               // 16B chunk index 0..31
                const int cg = bn + wn * 32 + nt * 8 + 2 * t;
                const float bz0 = bias[cg], bz1 = bias[cg + 1];
                const uint32_t cx = (uint32_t)((colc ^ (r0 & 7)) << 4);
                *(uint32_t*)((char*)sh + sw0 + cx) =
                    pack_h2((acc[mt][nt][0] + bz0) * oscale, (acc[mt][nt][1] + bz1) * oscale);
                *(uint32_t*)((char*)sh + sw1 + cx) =
                    pack_h2((acc[mt][nt][2] + bz0) * oscale, (acc[mt][nt][3] + bz1) * oscale);
            }
        }
        __syncthreads();
        const int orow = tid >> 2;                 // 0..127
        const int cq = tid & 3;
        const int grow = bm + orow;
        const int b = grow >> 11, l = grow & (SEQ - 1);
        __half* Ch = (__half*)C;
#pragma unroll
        for (int j = 0; j < 8; j++) {
            const int chunk = j * 4 + cq;          // 0..31, lanes coalesced 64B
            const uint32_t addr = (uint32_t)(orow << 9) + (uint32_t)(((chunk ^ (orow & 7))) << 4);
            const uint4 val = *(const uint4*)((const char*)sh + addr);
            const int col = bn + chunk * 8;
            const int h = col >> 6, d = col & 63;
            *(uint4*)&Ch[(((size_t)(b * HEADS + h) * SEQ + l) << 6) + d] = val;
        }
    } else {
        // float path: packed float2 stores
        float* Cf = (float*)C;
#pragma unroll
        for (int mt = 0; mt < 4; mt++) {
#pragma unroll
            for (int nt = 0; nt < 4; nt++) {
                const int r0 = bm + wm * 64 + mt * 16 + g;
                const int c0 = bn + wn * 32 + nt * 8 + 2 * t;
                const float bz0 = bias[c0], bz1 = bias[c0 + 1];
                float2 v0 = { acc[mt][nt][0] + bz0, acc[mt][nt][1] + bz1 };
                float2 v1 = { acc[mt][nt][2] + bz0, acc[mt][nt][3] + bz1 };
                *(float2*)&Cf[(size_t)r0 * D_MODEL + c0] = v0;
                *(float2*)&Cf[(size_t)(r0 + 8) * D_MODEL + c0] = v1;
            }
        }
    }
}

// ---------------- FP16 flash attention: 3-buffer cp.async, SW128, exp2 ----------------
#define QBYTES (128 * 128)
#define KBYTES (64 * 128)
#define KVBUF_B (2 * KBYTES)
#define FLASH_SMEM_B (QBYTES + 3 * KVBUF_B)  // 65536

__global__ __launch_bounds__(256) void flash_fp16(
    const __half* __restrict__ Q, const __half* __restrict__ K,
    const __half* __restrict__ V, __half* __restrict__ O)
{
    extern __shared__ __half sm[];
    const uint32_t sbase = smem_u32(sm);
    const uint32_t kvbase = sbase + QBYTES;

    const int tid = threadIdx.x;
    const int lane = tid & 31;
    const int w = tid >> 5;
    const int g = lane >> 2, t = lane & 3;
    const int bh = blockIdx.y;
    const int bx = blockIdx.x;
    const int q0 = bx * 128;

    const __half* Qb = Q + (size_t)bh * SEQ * DH;
    const __half* Kb = K + (size_t)bh * SEQ * DH;
    const __half* Vb = V + (size_t)bh * SEQ * DH;

    const int qrow = tid >> 1, qcb = (tid & 1) * 4;
    const int krow = tid >> 2, kcb = (tid & 3) * 2;
    const __half* Qg = Qb + (size_t)(q0 + qrow) * DH + (tid & 1) * 32;
    const __half* Kg = Kb + (size_t)krow * DH + (tid & 3) * 16;
    const __half* Vg = Vb + (size_t)krow * DH + (tid & 3) * 16;
    uint32_t qdst[4], kdst[2], vdst[2];
#pragma unroll
    for (int j = 0; j < 4; j++)
        qdst[j] = sbase + SWZ(qrow, qcb + j);
#pragma unroll
    for (int j = 0; j < 2; j++) {
        kdst[j] = kvbase + SWZ(krow, kcb + j);
        vdst[j] = kdst[j] + (uint32_t)KBYTES;
    }

    const int jmax = 2 * bx + 1;

#pragma unroll
    for (int j = 0; j < 4; j++) CPA16(qdst[j], Qg + j * 8);
#pragma unroll
    for (int j = 0; j < 2; j++) CPA16(kdst[j], Kg + j * 8);
#pragma unroll
    for (int j = 0; j < 2; j++) CPA16(vdst[j], Vg + j * 8);
    CPA_COMMIT();
    {
        const size_t koffg = (size_t)64 * DH;
#pragma unroll
        for (int j = 0; j < 2; j++) CPA16(kdst[j] + KVBUF_B, Kg + koffg + j * 8);
#pragma unroll
        for (int j = 0; j < 2; j++) CPA16(vdst[j] + KVBUF_B, Vg + koffg + j * 8);
        CPA_COMMIT();
    }

    const int lrow = (lane & 7) + ((lane >> 3) & 1) * 8;
    const int hi = lane >> 4;
    const int bhi = (lane >> 3) & 1;
    const int bn_lane = (lane & 7) + hi * 8;
    const int xq = lrow & 7;
    const int xk = bn_lane & 7;
    const uint32_t q_base = sbase + (uint32_t)((w * 16 + lrow) << 7);
    uint32_t k_base[4], v_base[4];
#pragma unroll
    for (int p = 0; p < 4; p++) {
        k_base[p] = kvbase + (uint32_t)((p * 16 + bn_lane) << 7);
        v_base[p] = kvbase + KBYTES + (uint32_t)((p * 16 + lrow) << 7);
    }

    float oacc[8][4];
#pragma unroll
    for (int dt = 0; dt < 8; dt++)
#pragma unroll
        for (int i = 0; i < 4; i++) oacc[dt][i] = 0.f;
    float m0 = -INFINITY, m1 = -INFINITY, l0 = 0.f, l1 = 0.f;

    const int qr = q0 + w * 16 + g;

    int buf = 0, pbuf = 2;
    for (int j = 0; j <= jmax; j++) {
        if (j + 1 <= jmax) { CPA_WAIT1(); } else { CPA_WAIT0(); }
        __syncthreads();
        if (j + 2 <= jmax) {
            const size_t koffg = (size_t)(j + 2) * 64 * DH;
            const uint32_t bo = (uint32_t)(pbuf * KVBUF_B);
#pragma unroll
            for (int jj = 0; jj < 2; jj++) CPA16(kdst[jj] + bo, Kg + koffg + jj * 8);
#pragma unroll
            for (int jj = 0; jj < 2; jj++) CPA16(vdst[jj] + bo, Vg + koffg + jj * 8);
            CPA_COMMIT();
        }
        const uint32_t bo = (uint32_t)(buf * KVBUF_B);
        const int k0 = j * 64;

        // S = Q K^T (Q pre-scaled by 0.125*log2e)
        float sacc[8][4];
#pragma unroll
        for (int nt = 0; nt < 8; nt++)
#pragma unroll
            for (int i = 0; i < 4; i++) sacc[nt][i] = 0.f;
#pragma unroll
        for (int kt = 0; kt < 4; kt++) {
            const uint32_t cq = (uint32_t)((((kt << 1) + hi) ^ xq) << 4);
            const uint32_t ck = (uint32_t)((((kt << 1) + bhi) ^ xk) << 4);
            uint32_t qf[4];
            ldsm4(qf, q_base + cq);
            uint32_t kb[8][2];
#pragma unroll
            for (int p = 0; p < 4; p++) {
                uint32_t r4[4];
                ldsm4(r4, k_base[p] + bo + ck);
                kb[2 * p][0] = r4[0];     kb[2 * p][1] = r4[1];
                kb[2 * p + 1][0] = r4[2]; kb[2 * p + 1][1] = r4[3];
            }
#pragma unroll
            for (int nt = 0; nt < 8; nt++)
                mma_f16(sacc[nt], qf, kb[nt]);
        }

        if (j >= 2 * bx) {
#pragma unroll
            for (int nt = 0; nt < 8; nt++) {
                const int c0 = k0 + nt * 8 + 2 * t;
#pragma unroll
                for (int i = 0; i < 4; i++) {
                    const int row = (i >> 1) ? qr + 8 : qr;
                    const int col = c0 + (i & 1);
                    if (col > row) sacc[nt][i] = -INFINITY;
                }
            }
        }

        // online softmax (base-2 domain)
        float mt0 = -INFINITY, mt1 = -INFINITY;
#pragma unroll
        for (int nt = 0; nt < 8; nt++) {
            mt0 = fmaxf(mt0, fmaxf(sacc[nt][0], sacc[nt][1]));
            mt1 = fmaxf(mt1, fmaxf(sacc[nt][2], sacc[nt][3]));
        }
        mt0 = fmaxf(mt0, __shfl_xor_sync(0xffffffffu, mt0, 1));
        mt0 = fmaxf(mt0, __shfl_xor_sync(0xffffffffu, mt0, 2));
        mt1 = fmaxf(mt1, __shfl_xor_sync(0xffffffffu, mt1, 1));
        mt1 = fmaxf(mt1, __shfl_xor_sync(0xffffffffu, mt1, 2));

        const float mn0 = fmaxf(m0, mt0), mn1 = fmaxf(m1, mt1);
        const float cor0 = exp2f(m0 - mn0), cor1 = exp2f(m1 - mn1);
        m0 = mn0; m1 = mn1;

        float rs0 = 0.f, rs1 = 0.f;
#pragma unroll
        for (int nt = 0; nt < 8; nt++) {
            const float p00 = exp2f(sacc[nt][0] - m0);
            const float p01 = exp2f(sacc[nt][1] - m0);
            const float p10 = exp2f(sacc[nt][2] - m1);
            const float p11 = exp2f(sacc[nt][3] - m1);
            rs0 += p00 + p01; rs1 += p10 + p11;
            sacc[nt][0] = p00; sacc[nt][1] = p01;
            sacc[nt][2] = p10; sacc[nt][3] = p11;
        }
        rs0 += __shfl_xor_sync(0xffffffffu, rs0, 1);
        rs0 += __shfl_xor_sync(0xffffffffu, rs0, 2);
        rs1 += __shfl_xor_sync(0xffffffffu, rs1, 1);
        rs1 += __shfl_xor_sync(0xffffffffu, rs1, 2);
        l0 = l0 * cor0 + rs0;
        l1 = l1 * cor1 + rs1;
        if (cor0 != 1.0f) {
#pragma unroll
            for (int dt = 0; dt < 8; dt++) { oacc[dt][0] *= cor0; oacc[dt][1] *= cor0; }
        }
        if (cor1 != 1.0f) {
#pragma unroll
            for (int dt = 0; dt < 8; dt++) { oacc[dt][2] *= cor1; oacc[dt][3] *= cor1; }
        }

        // O += P @ V
#pragma unroll
        for (int kt2 = 0; kt2 < 4; kt2++) {
            uint32_t pa[4];
            pa[0] = pack_h2(sacc[2 * kt2][0],     sacc[2 * kt2][1]);
            pa[1] = pack_h2(sacc[2 * kt2][2],     sacc[2 * kt2][3]);
            pa[2] = pack_h2(sacc[2 * kt2 + 1][0], sacc[2 * kt2 + 1][1]);
            pa[3] = pack_h2(sacc[2 * kt2 + 1][2], sacc[2 * kt2 + 1][3]);
#pragma unroll
            for (int pd = 0; pd < 4; pd++) {
                const uint32_t cv = (uint32_t)((((pd << 1) + hi) ^ xq) << 4);
                uint32_t r4[4];
                ldsm4t(r4, v_base[kt2] + bo + cv);
                uint32_t vb0[2] = { r4[0], r4[1] };
                uint32_t vb1[2] = { r4[2], r4[3] };
                mma_f16(oacc[2 * pd],     pa, vb0);
                mma_f16(oacc[2 * pd + 1], pa, vb1);
            }
        }
        if (++buf == 3) buf = 0;
        if (++pbuf == 3) pbuf = 0;
    }

    // write back into [B, L, D_MODEL] as fp16
    const int b = bh >> 4, h = bh & 15;
    const float inv0 = 1.f / l0, inv1 = 1.f / l1;
#pragma unroll
    for (int dt = 0; dt < 8; dt++) {
        const int col = h * DH + dt * 8 + 2 * t;
        __half* o0 = &O[(size_t)(b * SEQ + qr)     * D_MODEL + col];
        __half* o1 = &O[(size_t)(b * SEQ + qr + 8) * D_MODEL + col];
        *(uint32_t*)o0 = pack_h2(oacc[dt][0] * inv0, oacc[dt][1] * inv0);
        *(uint32_t*)o1 = pack_h2(oacc[dt][2] * inv1, oacc[dt][3] * inv1);
    }
}

// ---------------- launch ----------------
extern "C" void kernel_launch(void* const* d_in, const int* in_sizes, int n_in,
                              void* d_out, int out_size)
{
    const float* q  = (const float*)d_in[0];
    const float* k  = (const float*)d_in[1];
    const float* v  = (const float*)d_in[2];
    const float* Wq = (const float*)d_in[3];
    const float* bq = (const float*)d_in[4];
    const float* Wk = (const float*)d_in[5];
    const float* bk = (const float*)d_in[6];
    const float* Wv = (const float*)d_in[7];
    const float* bv = (const float*)d_in[8];
    const float* Wo = (const float*)d_in[9];
    const float* bo = (const float*)d_in[10];
    float* out = (float*)d_out;

    __half *qh, *kh, *vh, *att, *qc, *kc, *vc, *Wt;
    cudaGetSymbolAddress((void**)&qh,  g_qh);
    cudaGetSymbolAddress((void**)&kh,  g_kh);
    cudaGetSymbolAddress((void**)&vh,  g_vh);
    cudaGetSymbolAddress((void**)&att, g_att);
    cudaGetSymbolAddress((void**)&qc,  g_qc);
    cudaGetSymbolAddress((void**)&kc,  g_kc);
    cudaGetSymbolAddress((void**)&vc,  g_vc);
    cudaGetSymbolAddress((void**)&Wt,  g_Wt);

    tohalf3<<<dim3(M_TOTAL * D_MODEL / (256 * 4), 1, 3), 256>>>(q, k, v, qc, kc, vc);
    transpose_half4<<<dim3(32, 32, 4), 256>>>(Wq, Wk, Wv, Wo, Wt);

    cudaFuncSetAttribute(gemm_fp16<1>,
                         cudaFuncAttributeMaxDynamicSharedMemorySize, GEMM_SMEM_B);
    cudaFuncSetAttribute(gemm_fp16<0>,
                         cudaFuncAttributeMaxDynamicSharedMemorySize, GEMM_SMEM_B);
    cudaFuncSetAttribute(flash_fp16,
                         cudaFuncAttributeMaxDynamicSharedMemorySize, FLASH_SMEM_B);

    const size_t WSZ = (size_t)D_MODEL * D_MODEL;
    gemm_fp16<1><<<dim3(D_MODEL / 256, M_TOTAL / 128, 3), 512, GEMM_SMEM_B>>>(
        qc, kc, vc, Wt, Wt + WSZ, Wt + 2 * WSZ, bq, bk, bv, qh, kh, vh);

    flash_fp16<<<dim3(SEQ / 128, BATCH * HEADS), 256, FLASH_SMEM_B>>>(qh, kh, vh, att);

    gemm_fp16<0><<<dim3(D_MODEL / 256, M_TOTAL / 128, 1), 512, GEMM_SMEM_B>>>(
        att, att, att, Wt + 3 * WSZ, Wt + 3 * WSZ, Wt + 3 * WSZ,
        bo, bo, bo, out, out, out);
}

// round 15
// speedup vs baseline: 1.3126x; 1.0241x over previous
#include <cuda_runtime.h>
#include <cuda_fp16.h>
#include <math.h>
#include <stdint.h>

#define D_MODEL 1024
#define HEADS   16
#define DH      64
#define BATCH   4
#define SEQ     2048
#define M_TOTAL (BATCH * SEQ)   // 8192
#define LOG2E   1.44269504088896340736f

// ---------------- scratch (device globals: allocation-guard safe) ----------------
__device__ __half g_qh[(size_t)BATCH * HEADS * SEQ * DH];   // q pre-scaled by 0.125*log2e
__device__ __half g_kh[(size_t)BATCH * HEADS * SEQ * DH];
__device__ __half g_vh[(size_t)BATCH * HEADS * SEQ * DH];
__device__ __half g_att[(size_t)M_TOTAL * D_MODEL];
__device__ __half g_qc[(size_t)M_TOTAL * D_MODEL];
__device__ __half g_kc[(size_t)M_TOTAL * D_MODEL];
__device__ __half g_vc[(size_t)M_TOTAL * D_MODEL];
__device__ __half g_Wt[(size_t)4 * D_MODEL * D_MODEL];      // fp16, transposed [n][k]

// ---------------- helpers ----------------
__device__ __forceinline__ uint32_t smem_u32(const void* p) {
    uint32_t a;
    asm("{ .reg .u64 t; cvta.to.shared.u64 t, %1; cvt.u32.u64 %0, t; }" : "=r"(a) : "l"(p));
    return a;
}

__device__ __forceinline__ uint32_t pack_h2(float lo, float hi) {
    uint32_t r;
    asm("cvt.rn.f16x2.f32 %0, %1, %2;" : "=r"(r) : "f"(hi), "f"(lo));
    return r;
}

__device__ __forceinline__ void mma_f16(float c[4], const uint32_t a[4], const uint32_t b[2]) {
    asm("mma.sync.aligned.m16n8k16.row.col.f32.f16.f16.f32 "
        "{%0,%1,%2,%3}, {%4,%5,%6,%7}, {%8,%9}, {%0,%1,%2,%3};"
        : "+f"(c[0]), "+f"(c[1]), "+f"(c[2]), "+f"(c[3])
        : "r"(a[0]), "r"(a[1]), "r"(a[2]), "r"(a[3]), "r"(b[0]), "r"(b[1]));
}

__device__ __forceinline__ void ldsm4(uint32_t r[4], uint32_t saddr) {
    asm volatile("ldmatrix.sync.aligned.m8n8.x4.shared.b16 {%0,%1,%2,%3}, [%4];"
        : "=r"(r[0]), "=r"(r[1]), "=r"(r[2]), "=r"(r[3]) : "r"(saddr));
}

__device__ __forceinline__ void ldsm4t(uint32_t r[4], uint32_t saddr) {
    asm volatile("ldmatrix.sync.aligned.m8n8.x4.trans.shared.b16 {%0,%1,%2,%3}, [%4];"
        : "=r"(r[0]), "=r"(r[1]), "=r"(r[2]), "=r"(r[3]) : "r"(saddr));
}

#define CPA16(dst, src) asm volatile("cp.async.cg.shared.global [%0], [%1], 16;" :: "r"(dst), "l"(src))
#define CPA_COMMIT()    asm volatile("cp.async.commit_group;")
#define CPA_WAIT1()     asm volatile("cp.async.wait_group 1;")
#define CPA_WAIT0()     asm volatile("cp.async.wait_group 0;")

#define SWZ(row, chunk) ((uint32_t)(((row) << 7) + ((((chunk) ^ ((row) & 7))) << 4)))

// ---------------- prologue converts ----------------
__global__ __launch_bounds__(256) void tohalf3(
    const float* __restrict__ a, const float* __restrict__ b, const float* __restrict__ c,
    __half* __restrict__ oa, __half* __restrict__ ob, __half* __restrict__ oc)
{
    const int z = blockIdx.z;
    const float* in = (z == 0) ? a : (z == 1) ? b : c;
    __half* out     = (z == 0) ? oa : (z == 1) ? ob : oc;
    const size_t i = ((size_t)blockIdx.x * 256 + threadIdx.x) * 4;
    float4 v = *(const float4*)(in + i);
    uint2 u = { pack_h2(v.x, v.y), pack_h2(v.z, v.w) };
    *(uint2*)(out + i) = u;
}

__global__ __launch_bounds__(256) void transpose_half4(
    const float* __restrict__ w0, const float* __restrict__ w1,
    const float* __restrict__ w2, const float* __restrict__ w3,
    __half* __restrict__ outbase)
{
    const int z = blockIdx.z;
    const float* in = (z == 0) ? w0 : (z == 1) ? w1 : (z == 2) ? w2 : w3;
    __half* out = outbase + (size_t)z * D_MODEL * D_MODEL;

    __shared__ float tile[32][33];
    const int tx = threadIdx.x & 31, ty = threadIdx.x >> 5;
    const int x = blockIdx.x * 32 + tx;
    const int y = blockIdx.y * 32 + ty;
#pragma unroll
    for (int j = 0; j < 32; j += 8)
        tile[ty + j][tx] = in[(size_t)(y + j) * D_MODEL + x];
    __syncthreads();
    const int x2 = blockIdx.y * 32 + tx;
    const int y2 = blockIdx.x * 32 + ty;
#pragma unroll
    for (int j = 0; j < 32; j += 8)
        out[(size_t)(y2 + j) * D_MODEL + x2] = __float2half_rn(tile[tx][ty + j]);
}

// ---------------- FP16 GEMM: 256 threads, CTA 128x128, warp 64x32, 3-stage, 2 CTAs/SM ----------------
#define ABYTES (128 * 128)              // 16384
#define BBYTES (128 * 128)              // 16384
#define STAGE_B (ABYTES + BBYTES)       // 32768
#define GEMM_SMEM_B (3 * STAGE_B)       // 98304

template <int HEADSPLIT>
__global__ __launch_bounds__(256, 2) void gemm_fp16(
    const __half* __restrict__ A0, const __half* __restrict__ A1, const __half* __restrict__ A2,
    const __half* __restrict__ T0, const __half* __restrict__ T1, const __half* __restrict__ T2,
    const float* __restrict__ b0, const float* __restrict__ b1, const float* __restrict__ b2,
    void* __restrict__ C0, void* __restrict__ C1, void* __restrict__ C2)
{
    const int z = blockIdx.z;
    const __half* A   = (z == 0) ? A0 : (z == 1) ? A1 : A2;
    const __half* Wt  = (z == 0) ? T0 : (z == 1) ? T1 : T2;
    const float* bias = (z == 0) ? b0 : (z == 1) ? b1 : b2;
    void* C           = (z == 0) ? C0 : (z == 1) ? C1 : C2;
    const float oscale = (HEADSPLIT && z == 0) ? (0.125f * LOG2E) : 1.0f;

    extern __shared__ __half sh[];
    const uint32_t sbase = smem_u32(sh);
    const int tid = threadIdx.x;
    const int lane = tid & 31;
    const int w = tid >> 5;                      // 0..7
    const int g = lane >> 2, t = lane & 3;
    const int wm = w >> 2, wn = w & 3;           // warp tile 64x32
    const int bm = blockIdx.y * 128, bn = blockIdx.x * 128;

    float acc[4][4][4];
#pragma unroll
    for (int mt = 0; mt < 4; mt++)
#pragma unroll
        for (int nt = 0; nt < 4; nt++)
#pragma unroll
            for (int i = 0; i < 4; i++) acc[mt][nt][i] = 0.f;

    // staging: 128 rows x 8 chunks per matrix, 256 threads -> 4 chunks each
    const int srow = tid >> 1, scb = (tid & 1) * 4;
    const __half* Ag = A  + (size_t)(bm + srow) * D_MODEL + (tid & 1) * 32;
    const __half* Bg = Wt + (size_t)(bn + srow) * D_MODEL + (tid & 1) * 32;
    uint32_t adst[4], bdst[4];
#pragma unroll
    for (int j = 0; j < 4; j++) {
        adst[j] = sbase + SWZ(srow, scb + j);
        bdst[j] = sbase + ABYTES + SWZ(srow, scb + j);
    }

    // prologue: tiles 0,1 -> stages 0,1
#pragma unroll
    for (int p = 0; p < 2; p++) {
        const int k0 = p * 64;
        const uint32_t so = (uint32_t)(p * STAGE_B);
#pragma unroll
        for (int j = 0; j < 4; j++) CPA16(adst[j] + so, Ag + k0 + j * 8);
#pragma unroll
        for (int j = 0; j < 4; j++) CPA16(bdst[j] + so, Bg + k0 + j * 8);
        CPA_COMMIT();
    }

    // fragment bases
    const int lrow = (lane & 7) + ((lane >> 3) & 1) * 8;
    const int hi = lane >> 4;
    const int bhi = (lane >> 3) & 1;
    const int bn_lane = (lane & 7) + hi * 8;
    const int xa = lrow & 7;
    const int xb = bn_lane & 7;
    uint32_t a_base[4], b_base[2];
#pragma unroll
    for (int mt = 0; mt < 4; mt++)
        a_base[mt] = sbase + (uint32_t)((wm * 64 + mt * 16 + lrow) << 7);
#pragma unroll
    for (int p = 0; p < 2; p++)
        b_base[p] = sbase + ABYTES + (uint32_t)((wn * 32 + p * 16 + bn_lane) << 7);

    int s = 0, s2 = 2;
    for (int i = 0; i < 16; i++) {
        if (i + 1 < 16) { CPA_WAIT1(); } else { CPA_WAIT0(); }
        __syncthreads();
        if (i + 2 < 16) {
            const int k0 = (i + 2) * 64;
            const uint32_t so = (uint32_t)(s2 * STAGE_B);
#pragma unroll
            for (int j = 0; j < 4; j++) CPA16(adst[j] + so, Ag + k0 + j * 8);
#pragma unroll
            for (int j = 0; j < 4; j++) CPA16(bdst[j] + so, Bg + k0 + j * 8);
            CPA_COMMIT();
        }
        const uint32_t so = (uint32_t)(s * STAGE_B);
#pragma unroll
        for (int ks = 0; ks < 4; ks++) {
            const uint32_t ca = (uint32_t)((((ks << 1) + hi) ^ xa) << 4);
            const uint32_t cbk = (uint32_t)((((ks << 1) + bhi) ^ xb) << 4);
            uint32_t a[4][4], b[4][2];
#pragma unroll
            for (int mt = 0; mt < 4; mt++)
                ldsm4(a[mt], a_base[mt] + so + ca);
#pragma unroll
            for (int p = 0; p < 2; p++) {
                uint32_t r4[4];
                ldsm4(r4, b_base[p] + so + cbk);
                b[2 * p][0] = r4[0];     b[2 * p][1] = r4[1];
                b[2 * p + 1][0] = r4[2]; b[2 * p + 1][1] = r4[3];
            }
#pragma unroll
            for (int mt = 0; mt < 4; mt++)
#pragma unroll
                for (int nt = 0; nt < 4; nt++)
                    mma_f16(acc[mt][nt], a[mt], b[nt]);
        }
        if (++s == 3) s = 0;
        if (++s2 == 3) s2 = 0;
    }

    if (HEADSPLIT) {
        // ---- epilogue: smem bounce (32KB fp16 tile, 2 SW128 panels) -> coalesced 16B STG ----
        __syncthreads();
#pragma unroll
        for (int mt = 0; mt < 4; mt++) {
            const int r0 = wm * 64 + mt * 16 + g;
#pragma unroll
            for (int nt = 0; nt < 4; nt++) {
                const int colh = wn * 32 + nt * 8 + 2 * t;     // 0..127 (halves)
                const int pan = colh >> 6;                     // panel 0/1
                const int cin = (colh & 63) >> 3;              // 16B chunk in panel
                const int byo = (colh & 7) * 2;
                const int cg = bn + colh;
                const float bz0 = bias[cg], bz1 = bias[cg + 1];
                const uint32_t base0 = (uint32_t)(pan * 16384) + (uint32_t)(r0 << 7)
                                     + (uint32_t)((cin ^ (r0 & 7)) << 4) + (uint32_t)byo;
                const uint32_t base1 = (uint32_t)(pan * 16384) + (uint32_t)((r0 + 8) << 7)
                                     + (uint32_t)((cin ^ ((r0 + 8) & 7)) << 4) + (uint32_t)byo;
                *(uint32_t*)((char*)sh + base0) =
                    pack_h2((acc[mt][nt][0] + bz0) * oscale, (acc[mt][nt][1] + bz1) * oscale);
                *(uint32_t*)((char*)sh + base1) =
                    pack_h2((acc[mt][nt][2] + bz0) * oscale, (acc[mt][nt][3] + bz1) * oscale);
            }
        }
        __syncthreads();
        // write: warp covers 2 rows x 16 chunks; lanes 0..15 row0, 16..31 row1
        const int lrow2 = (tid >> 4);                // 0..15: (warp*2 + lane>>4)
        const int chunk = tid & 15;                  // 16B chunk 0..15
        __half* Ch = (__half*)C;
#pragma unroll
        for (int it = 0; it < 8; it++) {
            const int row = lrow2 + it * 16;         // 0..127
            const int pan = chunk >> 3, cin = chunk & 7;
            const uint32_t addr = (uint32_t)(pan * 16384) + (uint32_t)(row << 7)
                                + (uint32_t)((cin ^ (row & 7)) << 4);
            const uint4 val = *(const uint4*)((const char*)sh + addr);
            const int col = bn + chunk * 8;
            const int h = col >> 6, d = col & 63;
            const int grow = bm + row;
            const int b = grow >> 11, l = grow & (SEQ - 1);
            *(uint4*)&Ch[(((size_t)(b * HEADS + h) * SEQ + l) << 6) + d] = val;
        }
    } else {
        float* Cf = (float*)C;
#pragma unroll
        for (int mt = 0; mt < 4; mt++) {
#pragma unroll
            for (int nt = 0; nt < 4; nt++) {
                const int r0 = bm + wm * 64 + mt * 16 + g;
                const int c0 = bn + wn * 32 + nt * 8 + 2 * t;
                const float bz0 = bias[c0], bz1 = bias[c0 + 1];
                float2 v0 = { acc[mt][nt][0] + bz0, acc[mt][nt][1] + bz1 };
                float2 v1 = { acc[mt][nt][2] + bz0, acc[mt][nt][3] + bz1 };
                *(float2*)&Cf[(size_t)r0 * D_MODEL + c0] = v0;
                *(float2*)&Cf[(size_t)(r0 + 8) * D_MODEL + c0] = v1;
            }
        }
    }
}

// ---------------- FP16 flash attention: 3-buffer cp.async, SW128, exp2 ----------------
#define QBYTES (128 * 128)
#define KBYTES (64 * 128)
#define KVBUF_B (2 * KBYTES)
#define FLASH_SMEM_B (QBYTES + 3 * KVBUF_B)  // 65536

__global__ __launch_bounds__(256) void flash_fp16(
    const __half* __restrict__ Q, const __half* __restrict__ K,
    const __half* __restrict__ V, __half* __restrict__ O)
{
    extern __shared__ __half sm[];
    const uint32_t sbase = smem_u32(sm);
    const uint32_t kvbase = sbase + QBYTES;

    const int tid = threadIdx.x;
    const int lane = tid & 31;
    const int w = tid >> 5;
    const int g = lane >> 2, t = lane & 3;
    const int bh = blockIdx.y;
    const int bx = (int)(gridDim.x - 1) - (int)blockIdx.x;   // heavy tiles first
    const int q0 = bx * 128;

    const __half* Qb = Q + (size_t)bh * SEQ * DH;
    const __half* Kb = K + (size_t)bh * SEQ * DH;
    const __half* Vb = V + (size_t)bh * SEQ * DH;

    const int qrow = tid >> 1, qcb = (tid & 1) * 4;
    const int krow = tid >> 2, kcb = (tid & 3) * 2;
    const __half* Qg = Qb + (size_t)(q0 + qrow) * DH + (tid & 1) * 32;
    const __half* Kg = Kb + (size_t)krow * DH + (tid & 3) * 16;
    const __half* Vg = Vb + (size_t)krow * DH + (tid & 3) * 16;
    uint32_t qdst[4], kdst[2], vdst[2];
#pragma unroll
    for (int j = 0; j < 4; j++)
        qdst[j] = sbase + SWZ(qrow, qcb + j);
#pragma unroll
    for (int j = 0; j < 2; j++) {
        kdst[j] = kvbase + SWZ(krow, kcb + j);
        vdst[j] = kdst[j] + (uint32_t)KBYTES;
    }

    const int jmax = 2 * bx + 1;

#pragma unroll
    for (int j = 0; j < 4; j++) CPA16(qdst[j], Qg + j * 8);
#pragma unroll
    for (int j = 0; j < 2; j++) CPA16(kdst[j], Kg + j * 8);
#pragma unroll
    for (int j = 0; j < 2; j++) CPA16(vdst[j], Vg + j * 8);
    CPA_COMMIT();
    {
        const size_t koffg = (size_t)64 * DH;
#pragma unroll
        for (int j = 0; j < 2; j++) CPA16(kdst[j] + KVBUF_B, Kg + koffg + j * 8);
#pragma unroll
        for (int j = 0; j < 2; j++) CPA16(vdst[j] + KVBUF_B, Vg + koffg + j * 8);
        CPA_COMMIT();
    }

    const int lrow = (lane & 7) + ((lane >> 3) & 1) * 8;
    const int hi = lane >> 4;
    const int bhi = (lane >> 3) & 1;
    const int bn_lane = (lane & 7) + hi * 8;
    const int xq = lrow & 7;
    const int xk = bn_lane & 7;
    const uint32_t q_base = sbase + (uint32_t)((w * 16 + lrow) << 7);
    uint32_t k_base[4], v_base[4];
#pragma unroll
    for (int p = 0; p < 4; p++) {
        k_base[p] = kvbase + (uint32_t)((p * 16 + bn_lane) << 7);
        v_base[p] = kvbase + KBYTES + (uint32_t)((p * 16 + lrow) << 7);
    }

    float oacc[8][4];
#pragma unroll
    for (int dt = 0; dt < 8; dt++)
#pragma unroll
        for (int i = 0; i < 4; i++) oacc[dt][i] = 0.f;
    float m0 = -INFINITY, m1 = -INFINITY, l0 = 0.f, l1 = 0.f;

    const int qr = q0 + w * 16 + g;

    int buf = 0, pbuf = 2;
    for (int j = 0; j <= jmax; j++) {
        if (j + 1 <= jmax) { CPA_WAIT1(); } else { CPA_WAIT0(); }
        __syncthreads();
        if (j + 2 <= jmax) {
            const size_t koffg = (size_t)(j + 2) * 64 * DH;
            const uint32_t bo = (uint32_t)(pbuf * KVBUF_B);
#pragma unroll
            for (int jj = 0; jj < 2; jj++) CPA16(kdst[jj] + bo, Kg + koffg + jj * 8);
#pragma unroll
            for (int jj = 0; jj < 2; jj++) CPA16(vdst[jj] + bo, Vg + koffg + jj * 8);
            CPA_COMMIT();
        }
        const uint32_t bo = (uint32_t)(buf * KVBUF_B);
        const int k0 = j * 64;

        float sacc[8][4];
#pragma unroll
        for (int nt = 0; nt < 8; nt++)
#pragma unroll
            for (int i = 0; i < 4; i++) sacc[nt][i] = 0.f;
#pragma unroll
        for (int kt = 0; kt < 4; kt++) {
            const uint32_t cq = (uint32_t)((((kt << 1) + hi) ^ xq) << 4);
            const uint32_t ck = (uint32_t)((((kt << 1) + bhi) ^ xk) << 4);
            uint32_t qf[4];
            ldsm4(qf, q_base + cq);
            uint32_t kb[8][2];
#pragma unroll
            for (int p = 0; p < 4; p++) {
                uint32_t r4[4];
                ldsm4(r4, k_base[p] + bo + ck);
                kb[2 * p][0] = r4[0];     kb[2 * p][1] = r4[1];
                kb[2 * p + 1][0] = r4[2]; kb[2 * p + 1][1] = r4[3];
            }
#pragma unroll
            for (int nt = 0; nt < 8; nt++)
                mma_f16(sacc[nt], qf, kb[nt]);
        }

        if (j >= 2 * bx) {
#pragma unroll
            for (int nt = 0; nt < 8; nt++) {
                const int c0 = k0 + nt * 8 + 2 * t;
#pragma unroll
                for (int i = 0; i < 4; i++) {
                    const int row = (i >> 1) ? qr + 8 : qr;
                    const int col = c0 + (i & 1);
                    if (col > row) sacc[nt][i] = -INFINITY;
                }
            }
        }

        float mt0 = -INFINITY, mt1 = -INFINITY;
#pragma unroll
        for (int nt = 0; nt < 8; nt++) {
            mt0 = fmaxf(mt0, fmaxf(sacc[nt][0], sacc[nt][1]));
            mt1 = fmaxf(mt1, fmaxf(sacc[nt][2], sacc[nt][3]));
        }
        mt0 = fmaxf(mt0, __shfl_xor_sync(0xffffffffu, mt0, 1));
        mt0 = fmaxf(mt0, __shfl_xor_sync(0xffffffffu, mt0, 2));
        mt1 = fmaxf(mt1, __shfl_xor_sync(0xffffffffu, mt1, 1));
        mt1 = fmaxf(mt1, __shfl_xor_sync(0xffffffffu, mt1, 2));

        const float mn0 = fmaxf(m0, mt0), mn1 = fmaxf(m1, mt1);
        const float cor0 = exp2f(m0 - mn0), cor1 = exp2f(m1 - mn1);
        m0 = mn0; m1 = mn1;

        float rs0 = 0.f, rs1 = 0.f;
#pragma unroll
        for (int nt = 0; nt < 8; nt++) {
            const float p00 = exp2f(sacc[nt][0] - m0);
            const float p01 = exp2f(sacc[nt][1] - m0);
            const float p10 = exp2f(sacc[nt][2] - m1);
            const float p11 = exp2f(sacc[nt][3] - m1);
            rs0 += p00 + p01; rs1 += p10 + p11;
            sacc[nt][0] = p00; sacc[nt][1] = p01;
            sacc[nt][2] = p10; sacc[nt][3] = p11;
        }
        rs0 += __shfl_xor_sync(0xffffffffu, rs0, 1);
        rs0 += __shfl_xor_sync(0xffffffffu, rs0, 2);
        rs1 += __shfl_xor_sync(0xffffffffu, rs1, 1);
        rs1 += __shfl_xor_sync(0xffffffffu, rs1, 2);
        l0 = l0 * cor0 + rs0;
        l1 = l1 * cor1 + rs1;
        if (cor0 != 1.0f) {
#pragma unroll
            for (int dt = 0; dt < 8; dt++) { oacc[dt][0] *= cor0; oacc[dt][1] *= cor0; }
        }
        if (cor1 != 1.0f) {
#pragma unroll
            for (int dt = 0; dt < 8; dt++) { oacc[dt][2] *= cor1; oacc[dt][3] *= cor1; }
        }

#pragma unroll
        for (int kt2 = 0; kt2 < 4; kt2++) {
            uint32_t pa[4];
            pa[0] = pack_h2(sacc[2 * kt2][0],     sacc[2 * kt2][1]);
            pa[1] = pack_h2(sacc[2 * kt2][2],     sacc[2 * kt2][3]);
            pa[2] = pack_h2(sacc[2 * kt2 + 1][0], sacc[2 * kt2 + 1][1]);
            pa[3] = pack_h2(sacc[2 * kt2 + 1][2], sacc[2 * kt2 + 1][3]);
#pragma unroll
            for (int pd = 0; pd < 4; pd++) {
                const uint32_t cv = (uint32_t)((((pd << 1) + hi) ^ xq) << 4);
                uint32_t r4[4];
                ldsm4t(r4, v_base[kt2] + bo + cv);
                uint32_t vb0[2] = { r4[0], r4[1] };
                uint32_t vb1[2] = { r4[2], r4[3] };
                mma_f16(oacc[2 * pd],     pa, vb0);
                mma_f16(oacc[2 * pd + 1], pa, vb1);
            }
        }
        if (++buf == 3) buf = 0;
        if (++pbuf == 3) pbuf = 0;
    }

    const int b = bh >> 4, h = bh & 15;
    const float inv0 = 1.f / l0, inv1 = 1.f / l1;
#pragma unroll
    for (int dt = 0; dt < 8; dt++) {
        const int col = h * DH + dt * 8 + 2 * t;
        __half* o0 = &O[(size_t)(b * SEQ + qr)     * D_MODEL + col];
        __half* o1 = &O[(size_t)(b * SEQ + qr + 8) * D_MODEL + col];
        *(uint32_t*)o0 = pack_h2(oacc[dt][0] * inv0, oacc[dt][1] * inv0);
        *(uint32_t*)o1 = pack_h2(oacc[dt][2] * inv1, oacc[dt][3] * inv1);
    }
}

// ---------------- launch ----------------
extern "C" void kernel_launch(void* const* d_in, const int* in_sizes, int n_in,
                              void* d_out, int out_size)
{
    const float* q  = (const float*)d_in[0];
    const float* k  = (const float*)d_in[1];
    const float* v  = (const float*)d_in[2];
    const float* Wq = (const float*)d_in[3];
    const float* bq = (const float*)d_in[4];
    const float* Wk = (const float*)d_in[5];
    const float* bk = (const float*)d_in[6];
    const float* Wv = (const float*)d_in[7];
    const float* bv = (const float*)d_in[8];
    const float* Wo = (const float*)d_in[9];
    const float* bo = (const float*)d_in[10];
    float* out = (float*)d_out;

    __half *qh, *kh, *vh, *att, *qc, *kc, *vc, *Wt;
    cudaGetSymbolAddress((void**)&qh,  g_qh);
    cudaGetSymbolAddress((void**)&kh,  g_kh);
    cudaGetSymbolAddress((void**)&vh,  g_vh);
    cudaGetSymbolAddress((void**)&att, g_att);
    cudaGetSymbolAddress((void**)&qc,  g_qc);
    cudaGetSymbolAddress((void**)&kc,  g_kc);
    cudaGetSymbolAddress((void**)&vc,  g_vc);
    cudaGetSymbolAddress((void**)&Wt,  g_Wt);

    tohalf3<<<dim3(M_TOTAL * D_MODEL / (256 * 4), 1, 3), 256>>>(q, k, v, qc, kc, vc);
    transpose_half4<<<dim3(32, 32, 4), 256>>>(Wq, Wk, Wv, Wo, Wt);

    cudaFuncSetAttribute(gemm_fp16<1>,
                         cudaFuncAttributeMaxDynamicSharedMemorySize, GEMM_SMEM_B);
    cudaFuncSetAttribute(gemm_fp16<0>,
                         cudaFuncAttributeMaxDynamicSharedMemorySize, GEMM_SMEM_B);
    cudaFuncSetAttribute(flash_fp16,
                         cudaFuncAttributeMaxDynamicSharedMemorySize, FLASH_SMEM_B);

    const size_t WSZ = (size_t)D_MODEL * D_MODEL;
    gemm_fp16<1><<<dim3(D_MODEL / 128, M_TOTAL / 128, 3), 256, GEMM_SMEM_B>>>(
        qc, kc, vc, Wt, Wt + WSZ, Wt + 2 * WSZ, bq, bk, bv, qh, kh, vh);

    flash_fp16<<<dim3(SEQ / 128, BATCH * HEADS), 256, FLASH_SMEM_B>>>(qh, kh, vh, att);

    gemm_fp16<0><<<dim3(D_MODEL / 128, M_TOTAL / 128, 1), 256, GEMM_SMEM_B>>>(
        att, att, att, Wt + 3 * WSZ, Wt + 3 * WSZ, Wt + 3 * WSZ,
        bo, bo, bo, out, out, out);
}

// round 17
// speedup vs baseline: 1.3173x; 1.0036x over previous
#include <cuda_runtime.h>
#include <cuda_fp16.h>
#include <math.h>
#include <stdint.h>

#define D_MODEL 1024
#define HEADS   16
#define DH      64
#define BATCH   4
#define SEQ     2048
#define M_TOTAL (BATCH * SEQ)   // 8192
#define LOG2E   1.44269504088896340736f

// ---------------- scratch (device globals: allocation-guard safe) ----------------
__device__ __half g_qh[(size_t)BATCH * HEADS * SEQ * DH];   // q pre-scaled by 0.125*log2e
__device__ __half g_kh[(size_t)BATCH * HEADS * SEQ * DH];
__device__ __half g_vh[(size_t)BATCH * HEADS * SEQ * DH];
__device__ __half g_att[(size_t)M_TOTAL * D_MODEL];
__device__ __half g_qc[(size_t)M_TOTAL * D_MODEL];
__device__ __half g_kc[(size_t)M_TOTAL * D_MODEL];
__device__ __half g_vc[(size_t)M_TOTAL * D_MODEL];
__device__ __half g_Wt[(size_t)4 * D_MODEL * D_MODEL];      // fp16, transposed [n][k]

// ---------------- helpers ----------------
__device__ __forceinline__ uint32_t smem_u32(const void* p) {
    uint32_t a;
    asm("{ .reg .u64 t; cvta.to.shared.u64 t, %1; cvt.u32.u64 %0, t; }" : "=r"(a) : "l"(p));
    return a;
}

__device__ __forceinline__ uint32_t pack_h2(float lo, float hi) {
    uint32_t r;
    asm("cvt.rn.f16x2.f32 %0, %1, %2;" : "=r"(r) : "f"(hi), "f"(lo));
    return r;
}

__device__ __forceinline__ void mma_f16(float c[4], const uint32_t a[4], const uint32_t b[2]) {
    asm("mma.sync.aligned.m16n8k16.row.col.f32.f16.f16.f32 "
        "{%0,%1,%2,%3}, {%4,%5,%6,%7}, {%8,%9}, {%0,%1,%2,%3};"
        : "+f"(c[0]), "+f"(c[1]), "+f"(c[2]), "+f"(c[3])
        : "r"(a[0]), "r"(a[1]), "r"(a[2]), "r"(a[3]), "r"(b[0]), "r"(b[1]));
}

__device__ __forceinline__ void ldsm4(uint32_t r[4], uint32_t saddr) {
    asm volatile("ldmatrix.sync.aligned.m8n8.x4.shared.b16 {%0,%1,%2,%3}, [%4];"
        : "=r"(r[0]), "=r"(r[1]), "=r"(r[2]), "=r"(r[3]) : "r"(saddr));
}

__device__ __forceinline__ void ldsm4t(uint32_t r[4], uint32_t saddr) {
    asm volatile("ldmatrix.sync.aligned.m8n8.x4.trans.shared.b16 {%0,%1,%2,%3}, [%4];"
        : "=r"(r[0]), "=r"(r[1]), "=r"(r[2]), "=r"(r[3]) : "r"(saddr));
}

#define CPA16(dst, src) asm volatile("cp.async.cg.shared.global [%0], [%1], 16;" :: "r"(dst), "l"(src))
#define CPA_COMMIT()    asm volatile("cp.async.commit_group;")
#define CPA_WAIT1()     asm volatile("cp.async.wait_group 1;")
#define CPA_WAIT0()     asm volatile("cp.async.wait_group 0;")

#define SWZ(row, chunk) ((uint32_t)(((row) << 7) + ((((chunk) ^ ((row) & 7))) << 4)))

// ---------------- prologue converts ----------------
__global__ __launch_bounds__(256) void tohalf3(
    const float* __restrict__ a, const float* __restrict__ b, const float* __restrict__ c,
    __half* __restrict__ oa, __half* __restrict__ ob, __half* __restrict__ oc)
{
    const int z = blockIdx.z;
    const float* in = (z == 0) ? a : (z == 1) ? b : c;
    __half* out     = (z == 0) ? oa : (z == 1) ? ob : oc;
    const size_t i = ((size_t)blockIdx.x * 256 + threadIdx.x) * 4;
    float4 v = *(const float4*)(in + i);
    uint2 u = { pack_h2(v.x, v.y), pack_h2(v.z, v.w) };
    *(uint2*)(out + i) = u;
}

__global__ __launch_bounds__(256) void transpose_half4(
    const float* __restrict__ w0, const float* __restrict__ w1,
    const float* __restrict__ w2, const float* __restrict__ w3,
    __half* __restrict__ outbase)
{
    const int z = blockIdx.z;
    const float* in = (z == 0) ? w0 : (z == 1) ? w1 : (z == 2) ? w2 : w3;
    __half* out = outbase + (size_t)z * D_MODEL * D_MODEL;

    __shared__ float tile[32][33];
    const int tx = threadIdx.x & 31, ty = threadIdx.x >> 5;
    const int x = blockIdx.x * 32 + tx;
    const int y = blockIdx.y * 32 + ty;
#pragma unroll
    for (int j = 0; j < 32; j += 8)
        tile[ty + j][tx] = in[(size_t)(y + j) * D_MODEL + x];
    __syncthreads();
    const int x2 = blockIdx.y * 32 + tx;
    const int y2 = blockIdx.x * 32 + ty;
#pragma unroll
    for (int j = 0; j < 32; j += 8)
        out[(size_t)(y2 + j) * D_MODEL + x2] = __float2half_rn(tile[tx][ty + j]);
}

// ---------------- FP16 GEMM: 256 threads, CTA 128x128, warp 64x32, 3-stage, 2 CTAs/SM ----------------
#define ABYTES (128 * 128)              // 16384
#define BBYTES (128 * 128)              // 16384
#define STAGE_B (ABYTES + BBYTES)       // 32768
#define GEMM_SMEM_B (3 * STAGE_B)       // 98304

template <int HEADSPLIT>
__global__ __launch_bounds__(256, 2) void gemm_fp16(
    const __half* __restrict__ A0, const __half* __restrict__ A1, const __half* __restrict__ A2,
    const __half* __restrict__ T0, const __half* __restrict__ T1, const __half* __restrict__ T2,
    const float* __restrict__ b0, const float* __restrict__ b1, const float* __restrict__ b2,
    void* __restrict__ C0, void* __restrict__ C1, void* __restrict__ C2)
{
    const int z = blockIdx.z;
    const __half* A   = (z == 0) ? A0 : (z == 1) ? A1 : A2;
    const __half* Wt  = (z == 0) ? T0 : (z == 1) ? T1 : T2;
    const float* bias = (z == 0) ? b0 : (z == 1) ? b1 : b2;
    void* C           = (z == 0) ? C0 : (z == 1) ? C1 : C2;
    const float oscale = (HEADSPLIT && z == 0) ? (0.125f * LOG2E) : 1.0f;

    extern __shared__ __half sh[];
    const uint32_t sbase = smem_u32(sh);
    const int tid = threadIdx.x;
    const int lane = tid & 31;
    const int w = tid >> 5;
    const int g = lane >> 2, t = lane & 3;
    const int wm = w >> 2, wn = w & 3;
    const int bm = blockIdx.y * 128, bn = blockIdx.x * 128;

    float acc[4][4][4];
#pragma unroll
    for (int mt = 0; mt < 4; mt++)
#pragma unroll
        for (int nt = 0; nt < 4; nt++)
#pragma unroll
            for (int i = 0; i < 4; i++) acc[mt][nt][i] = 0.f;

    const int srow = tid >> 1, scb = (tid & 1) * 4;
    const __half* Ag = A  + (size_t)(bm + srow) * D_MODEL + (tid & 1) * 32;
    const __half* Bg = Wt + (size_t)(bn + srow) * D_MODEL + (tid & 1) * 32;
    uint32_t adst[4], bdst[4];
#pragma unroll
    for (int j = 0; j < 4; j++) {
        adst[j] = sbase + SWZ(srow, scb + j);
        bdst[j] = sbase + ABYTES + SWZ(srow, scb + j);
    }

#pragma unroll
    for (int p = 0; p < 2; p++) {
        const int k0 = p * 64;
        const uint32_t so = (uint32_t)(p * STAGE_B);
#pragma unroll
        for (int j = 0; j < 4; j++) CPA16(adst[j] + so, Ag + k0 + j * 8);
#pragma unroll
        for (int j = 0; j < 4; j++) CPA16(bdst[j] + so, Bg + k0 + j * 8);
        CPA_COMMIT();
    }

    const int lrow = (lane & 7) + ((lane >> 3) & 1) * 8;
    const int hi = lane >> 4;
    const int bhi = (lane >> 3) & 1;
    const int bn_lane = (lane & 7) + hi * 8;
    const int xa = lrow & 7;
    const int xb = bn_lane & 7;
    uint32_t a_base[4], b_base[2];
#pragma unroll
    for (int mt = 0; mt < 4; mt++)
        a_base[mt] = sbase + (uint32_t)((wm * 64 + mt * 16 + lrow) << 7);
#pragma unroll
    for (int p = 0; p < 2; p++)
        b_base[p] = sbase + ABYTES + (uint32_t)((wn * 32 + p * 16 + bn_lane) << 7);

    int s = 0, s2 = 2;
    for (int i = 0; i < 16; i++) {
        if (i + 1 < 16) { CPA_WAIT1(); } else { CPA_WAIT0(); }
        __syncthreads();
        if (i + 2 < 16) {
            const int k0 = (i + 2) * 64;
            const uint32_t so = (uint32_t)(s2 * STAGE_B);
#pragma unroll
            for (int j = 0; j < 4; j++) CPA16(adst[j] + so, Ag + k0 + j * 8);
#pragma unroll
            for (int j = 0; j < 4; j++) CPA16(bdst[j] + so, Bg + k0 + j * 8);
            CPA_COMMIT();
        }
        const uint32_t so = (uint32_t)(s * STAGE_B);
#pragma unroll
        for (int ks = 0; ks < 4; ks++) {
            const uint32_t ca = (uint32_t)((((ks << 1) + hi) ^ xa) << 4);
            const uint32_t cbk = (uint32_t)((((ks << 1) + bhi) ^ xb) << 4);
            uint32_t a[4][4], b[4][2];
#pragma unroll
            for (int mt = 0; mt < 4; mt++)
                ldsm4(a[mt], a_base[mt] + so + ca);
#pragma unroll
            for (int p = 0; p < 2; p++) {
                uint32_t r4[4];
                ldsm4(r4, b_base[p] + so + cbk);
                b[2 * p][0] = r4[0];     b[2 * p][1] = r4[1];
                b[2 * p + 1][0] = r4[2]; b[2 * p + 1][1] = r4[3];
            }
#pragma unroll
            for (int mt = 0; mt < 4; mt++)
#pragma unroll
                for (int nt = 0; nt < 4; nt++)
                    mma_f16(acc[mt][nt], a[mt], b[nt]);
        }
        if (++s == 3) s = 0;
        if (++s2 == 3) s2 = 0;
    }

    if (HEADSPLIT) {
        __syncthreads();
#pragma unroll
        for (int mt = 0; mt < 4; mt++) {
            const int r0 = wm * 64 + mt * 16 + g;
#pragma unroll
            for (int nt = 0; nt < 4; nt++) {
                const int colh = wn * 32 + nt * 8 + 2 * t;
                const int pan = colh >> 6;
                const int cin = (colh & 63) >> 3;
                const int byo = (colh & 7) * 2;
                const int cg = bn + colh;
                const float bz0 = bias[cg], bz1 = bias[cg + 1];
                const uint32_t base0 = (uint32_t)(pan * 16384) + (uint32_t)(r0 << 7)
                                     + (uint32_t)((cin ^ (r0 & 7)) << 4) + (uint32_t)byo;
                const uint32_t base1 = (uint32_t)(pan * 16384) + (uint32_t)((r0 + 8) << 7)
                                     + (uint32_t)((cin ^ ((r0 + 8) & 7)) << 4) + (uint32_t)byo;
                *(uint32_t*)((char*)sh + base0) =
                    pack_h2((acc[mt][nt][0] + bz0) * oscale, (acc[mt][nt][1] + bz1) * oscale);
                *(uint32_t*)((char*)sh + base1) =
                    pack_h2((acc[mt][nt][2] + bz0) * oscale, (acc[mt][nt][3] + bz1) * oscale);
            }
        }
        __syncthreads();
        const int lrow2 = (tid >> 4);
        const int chunk = tid & 15;
        __half* Ch = (__half*)C;
#pragma unroll
        for (int it = 0; it < 8; it++) {
            const int row = lrow2 + it * 16;
            const int pan = chunk >> 3, cin = chunk & 7;
            const uint32_t addr = (uint32_t)(pan * 16384) + (uint32_t)(row << 7)
                                + (uint32_t)((cin ^ (row & 7)) << 4);
            const uint4 val = *(const uint4*)((const char*)sh + addr);
            const int col = bn + chunk * 8;
            const int h = col >> 6, d = col & 63;
            const int grow = bm + row;
            const int b = grow >> 11, l = grow & (SEQ - 1);
            *(uint4*)&Ch[(((size_t)(b * HEADS + h) * SEQ + l) << 6) + d] = val;
        }
    } else {
        float* Cf = (float*)C;
#pragma unroll
        for (int mt = 0; mt < 4; mt++) {
#pragma unroll
            for (int nt = 0; nt < 4; nt++) {
                const int r0 = bm + wm * 64 + mt * 16 + g;
                const int c0 = bn + wn * 32 + nt * 8 + 2 * t;
                const float bz0 = bias[c0], bz1 = bias[c0 + 1];
                float2 v0 = { acc[mt][nt][0] + bz0, acc[mt][nt][1] + bz1 };
                float2 v1 = { acc[mt][nt][2] + bz0, acc[mt][nt][3] + bz1 };
                *(float2*)&Cf[(size_t)r0 * D_MODEL + c0] = v0;
                *(float2*)&Cf[(size_t)(r0 + 8) * D_MODEL + c0] = v1;
            }
        }
    }
}

// ---------------- FP16 flash attention: streamed exp->PV (MUFU/HMMA overlap) ----------------
#define QBYTES (128 * 128)
#define KBYTES (64 * 128)
#define KVBUF_B (2 * KBYTES)
#define FLASH_SMEM_B (QBYTES + 3 * KVBUF_B)  // 65536

__global__ __launch_bounds__(256) void flash_fp16(
    const __half* __restrict__ Q, const __half* __restrict__ K,
    const __half* __restrict__ V, __half* __restrict__ O)
{
    extern __shared__ __half sm[];
    const uint32_t sbase = smem_u32(sm);
    const uint32_t kvbase = sbase + QBYTES;

    const int tid = threadIdx.x;
    const int lane = tid & 31;
    const int w = tid >> 5;
    const int g = lane >> 2, t = lane & 3;
    const int bh = blockIdx.y;
    const int bx = (int)(gridDim.x - 1) - (int)blockIdx.x;   // heavy tiles first
    const int q0 = bx * 128;

    const __half* Qb = Q + (size_t)bh * SEQ * DH;
    const __half* Kb = K + (size_t)bh * SEQ * DH;
    const __half* Vb = V + (size_t)bh * SEQ * DH;

    const int qrow = tid >> 1, qcb = (tid & 1) * 4;
    const int krow = tid >> 2, kcb = (tid & 3) * 2;
    const __half* Qg = Qb + (size_t)(q0 + qrow) * DH + (tid & 1) * 32;
    const __half* Kg = Kb + (size_t)krow * DH + (tid & 3) * 16;
    const __half* Vg = Vb + (size_t)krow * DH + (tid & 3) * 16;
    uint32_t qdst[4], kdst[2], vdst[2];
#pragma unroll
    for (int j = 0; j < 4; j++)
        qdst[j] = sbase + SWZ(qrow, qcb + j);
#pragma unroll
    for (int j = 0; j < 2; j++) {
        kdst[j] = kvbase + SWZ(krow, kcb + j);
        vdst[j] = kdst[j] + (uint32_t)KBYTES;
    }

    const int jmax = 2 * bx + 1;

#pragma unroll
    for (int j = 0; j < 4; j++) CPA16(qdst[j], Qg + j * 8);
#pragma unroll
    for (int j = 0; j < 2; j++) CPA16(kdst[j], Kg + j * 8);
#pragma unroll
    for (int j = 0; j < 2; j++) CPA16(vdst[j], Vg + j * 8);
    CPA_COMMIT();
    {
        const size_t koffg = (size_t)64 * DH;
#pragma unroll
        for (int j = 0; j < 2; j++) CPA16(kdst[j] + KVBUF_B, Kg + koffg + j * 8);
#pragma unroll
        for (int j = 0; j < 2; j++) CPA16(vdst[j] + KVBUF_B, Vg + koffg + j * 8);
        CPA_COMMIT();
    }

    const int lrow = (lane & 7) + ((lane >> 3) & 1) * 8;
    const int hi = lane >> 4;
    const int bhi = (lane >> 3) & 1;
    const int bn_lane = (lane & 7) + hi * 8;
    const int xq = lrow & 7;
    const int xk = bn_lane & 7;
    const uint32_t q_base = sbase + (uint32_t)((w * 16 + lrow) << 7);
    uint32_t k_base[4], v_base[4];
#pragma unroll
    for (int p = 0; p < 4; p++) {
        k_base[p] = kvbase + (uint32_t)((p * 16 + bn_lane) << 7);
        v_base[p] = kvbase + KBYTES + (uint32_t)((p * 16 + lrow) << 7);
    }

    float oacc[8][4];
#pragma unroll
    for (int dt = 0; dt < 8; dt++)
#pragma unroll
        for (int i = 0; i < 4; i++) oacc[dt][i] = 0.f;
    float m0 = -INFINITY, m1 = -INFINITY, l0 = 0.f, l1 = 0.f;

    const int qr = q0 + w * 16 + g;

    int buf = 0, pbuf = 2;
    for (int j = 0; j <= jmax; j++) {
        if (j + 1 <= jmax) { CPA_WAIT1(); } else { CPA_WAIT0(); }
        __syncthreads();
        if (j + 2 <= jmax) {
            const size_t koffg = (size_t)(j + 2) * 64 * DH;
            const uint32_t bo = (uint32_t)(pbuf * KVBUF_B);
#pragma unroll
            for (int jj = 0; jj < 2; jj++) CPA16(kdst[jj] + bo, Kg + koffg + jj * 8);
#pragma unroll
            for (int jj = 0; jj < 2; jj++) CPA16(vdst[jj] + bo, Vg + koffg + jj * 8);
            CPA_COMMIT();
        }
        const uint32_t bo = (uint32_t)(buf * KVBUF_B);
        const int k0 = j * 64;

        // ---- S = Q K^T (Q pre-scaled by 0.125*log2e) ----
        float sacc[8][4];
#pragma unroll
        for (int nt = 0; nt < 8; nt++)
#pragma unroll
            for (int i = 0; i < 4; i++) sacc[nt][i] = 0.f;
#pragma unroll
        for (int kt = 0; kt < 4; kt++) {
            const uint32_t cq = (uint32_t)((((kt << 1) + hi) ^ xq) << 4);
            const uint32_t ck = (uint32_t)((((kt << 1) + bhi) ^ xk) << 4);
            uint32_t qf[4];
            ldsm4(qf, q_base + cq);
            uint32_t kb[8][2];
#pragma unroll
            for (int p = 0; p < 4; p++) {
                uint32_t r4[4];
                ldsm4(r4, k_base[p] + bo + ck);
                kb[2 * p][0] = r4[0];     kb[2 * p][1] = r4[1];
                kb[2 * p + 1][0] = r4[2]; kb[2 * p + 1][1] = r4[3];
            }
#pragma unroll
            for (int nt = 0; nt < 8; nt++)
                mma_f16(sacc[nt], qf, kb[nt]);
        }

        // ---- causal mask (diagonal-adjacent tiles only) ----
        if (j >= 2 * bx) {
#pragma unroll
            for (int nt = 0; nt < 8; nt++) {
                const int c0 = k0 + nt * 8 + 2 * t;
#pragma unroll
                for (int i = 0; i < 4; i++) {
                    const int row = (i >> 1) ? qr + 8 : qr;
                    const int col = c0 + (i & 1);
                    if (col > row) sacc[nt][i] = -INFINITY;
                }
            }
        }

        // ---- running max ----
        float mt0 = -INFINITY, mt1 = -INFINITY;
#pragma unroll
        for (int nt = 0; nt < 8; nt++) {
            mt0 = fmaxf(mt0, fmaxf(sacc[nt][0], sacc[nt][1]));
            mt1 = fmaxf(mt1, fmaxf(sacc[nt][2], sacc[nt][3]));
        }
        mt0 = fmaxf(mt0, __shfl_xor_sync(0xffffffffu, mt0, 1));
        mt0 = fmaxf(mt0, __shfl_xor_sync(0xffffffffu, mt0, 2));
        mt1 = fmaxf(mt1, __shfl_xor_sync(0xffffffffu, mt1, 1));
        mt1 = fmaxf(mt1, __shfl_xor_sync(0xffffffffu, mt1, 2));

        const float mn0 = fmaxf(m0, mt0), mn1 = fmaxf(m1, mt1);
        const float cor0 = exp2f(m0 - mn0), cor1 = exp2f(m1 - mn1);
        m0 = mn0; m1 = mn1;

        // rescale O first (independent of exps) — PV below accumulates on top
        if (cor0 != 1.0f) {
#pragma unroll
            for (int dt = 0; dt < 8; dt++) { oacc[dt][0] *= cor0; oacc[dt][1] *= cor0; }
        }
        if (cor1 != 1.0f) {
#pragma unroll
            for (int dt = 0; dt < 8; dt++) { oacc[dt][2] *= cor1; oacc[dt][3] *= cor1; }
        }

        // ---- streamed exp -> pack -> PV per 16-key group (MUFU overlaps HMMA) ----
        float rs0 = 0.f, rs1 = 0.f;
#pragma unroll
        for (int kt2 = 0; kt2 < 4; kt2++) {
            const int n0 = 2 * kt2, n1 = 2 * kt2 + 1;
            const float p00 = exp2f(sacc[n0][0] - m0);
            const float p01 = exp2f(sacc[n0][1] - m0);
            const float p02 = exp2f(sacc[n0][2] - m1);
            const float p03 = exp2f(sacc[n0][3] - m1);
            const float p10 = exp2f(sacc[n1][0] - m0);
            const float p11 = exp2f(sacc[n1][1] - m0);
            const float p12 = exp2f(sacc[n1][2] - m1);
            const float p13 = exp2f(sacc[n1][3] - m1);
            rs0 += p00 + p01 + p10 + p11;
            rs1 += p02 + p03 + p12 + p13;
            uint32_t pa[4];
            pa[0] = pack_h2(p00, p01);
            pa[1] = pack_h2(p02, p03);
            pa[2] = pack_h2(p10, p11);
            pa[3] = pack_h2(p12, p13);
#pragma unroll
            for (int pd = 0; pd < 4; pd++) {
                const uint32_t cv = (uint32_t)((((pd << 1) + hi) ^ xq) << 4);
                uint32_t r4[4];
                ldsm4t(r4, v_base[kt2] + bo + cv);
                uint32_t vb0[2] = { r4[0], r4[1] };
                uint32_t vb1[2] = { r4[2], r4[3] };
                mma_f16(oacc[2 * pd],     pa, vb0);
                mma_f16(oacc[2 * pd + 1], pa, vb1);
            }
        }

        // ---- finish softmax bookkeeping ----
        rs0 += __shfl_xor_sync(0xffffffffu, rs0, 1);
        rs0 += __shfl_xor_sync(0xffffffffu, rs0, 2);
        rs1 += __shfl_xor_sync(0xffffffffu, rs1, 1);
        rs1 += __shfl_xor_sync(0xffffffffu, rs1, 2);
        l0 = l0 * cor0 + rs0;
        l1 = l1 * cor1 + rs1;

        if (++buf == 3) buf = 0;
        if (++pbuf == 3) pbuf = 0;
    }

    const int b = bh >> 4, h = bh & 15;
    const float inv0 = 1.f / l0, inv1 = 1.f / l1;
#pragma unroll
    for (int dt = 0; dt < 8; dt++) {
        const int col = h * DH + dt * 8 + 2 * t;
        __half* o0 = &O[(size_t)(b * SEQ + qr)     * D_MODEL + col];
        __half* o1 = &O[(size_t)(b * SEQ + qr + 8) * D_MODEL + col];
        *(uint32_t*)o0 = pack_h2(oacc[dt][0] * inv0, oacc[dt][1] * inv0);
        *(uint32_t*)o1 = pack_h2(oacc[dt][2] * inv1, oacc[dt][3] * inv1);
    }
}

// ---------------- launch ----------------
extern "C" void kernel_launch(void* const* d_in, const int* in_sizes, int n_in,
                              void* d_out, int out_size)
{
    const float* q  = (const float*)d_in[0];
    const float* k  = (const float*)d_in[1];
    const float* v  = (const float*)d_in[2];
    const float* Wq = (const float*)d_in[3];
    const float* bq = (const float*)d_in[4];
    const float* Wk = (const float*)d_in[5];
    const float* bk = (const float*)d_in[6];
    const float* Wv = (const float*)d_in[7];
    const float* bv = (const float*)d_in[8];
    const float* Wo = (const float*)d_in[9];
    const float* bo = (const float*)d_in[10];
    float* out = (float*)d_out;

    __half *qh, *kh, *vh, *att, *qc, *kc, *vc, *Wt;
    cudaGetSymbolAddress((void**)&qh,  g_qh);
    cudaGetSymbolAddress((void**)&kh,  g_kh);
    cudaGetSymbolAddress((void**)&vh,  g_vh);
    cudaGetSymbolAddress((void**)&att, g_att);
    cudaGetSymbolAddress((void**)&qc,  g_qc);
    cudaGetSymbolAddress((void**)&kc,  g_kc);
    cudaGetSymbolAddress((void**)&vc,  g_vc);
    cudaGetSymbolAddress((void**)&Wt,  g_Wt);

    tohalf3<<<dim3(M_TOTAL * D_MODEL / (256 * 4), 1, 3), 256>>>(q, k, v, qc, kc, vc);
    transpose_half4<<<dim3(32, 32, 4), 256>>>(Wq, Wk, Wv, Wo, Wt);

    cudaFuncSetAttribute(gemm_fp16<1>,
                         cudaFuncAttributeMaxDynamicSharedMemorySize, GEMM_SMEM_B);
    cudaFuncSetAttribute(gemm_fp16<0>,
                         cudaFuncAttributeMaxDynamicSharedMemorySize, GEMM_SMEM_B);
    cudaFuncSetAttribute(flash_fp16,
                         cudaFuncAttributeMaxDynamicSharedMemorySize, FLASH_SMEM_B);

    const size_t WSZ = (size_t)D_MODEL * D_MODEL;
    gemm_fp16<1><<<dim3(D_MODEL / 128, M_TOTAL / 128, 3), 256, GEMM_SMEM_B>>>(
        qc, kc, vc, Wt, Wt + WSZ, Wt + 2 * WSZ, bq, bk, bv, qh, kh, vh);

    flash_fp16<<<dim3(SEQ / 128, BATCH * HEADS), 256, FLASH_SMEM_B>>>(qh, kh, vh, att);

    gemm_fp16<0><<<dim3(D_MODEL / 128, M_TOTAL / 128, 1), 256, GEMM_SMEM_B>>>(
        att, att, att, Wt + 3 * WSZ, Wt + 3 * WSZ, Wt + 3 * WSZ,
        bo, bo, bo, out, out, out);
}